// round 10
// baseline (speedup 1.0000x reference)
#include <cuda_runtime.h>
#include <math.h>
#include <stdint.h>
#include <mma.h>

using namespace nvcuda;

// ---------------- problem constants ----------------
#define HH 384
#define BB 16
#define CI 64
#define EE 768

// ---------------- scratch (device globals, no allocation) ----------------
// g_f1: conv1 output (NCHW fp32) during stem; AFTER conv2 it is reused (overlay)
// as the NHWC tf32 copy of f2 for the coarse GEMM. Same size, no new big global.
__device__ float g_f1[(size_t)BB*CI*HH*HH];
__device__ float g_f2[(size_t)BB*CI*HH*HH];          // conv2 out, NCHW fp32 (exact)
__device__ float g_dgath[(size_t)4096*EE];           // gathered detail conv outputs
__device__ float g_scores[BB*576];
__device__ int   g_topk[BB*64];
__device__ float g_mbias[EE];                        // effective merge bias
__device__ float g_cwt[(size_t)EE*16384];            // coarse w [e][pyx][c], tf32 (50 MB)

__device__ __forceinline__ float gelu_f(float v) { return v * normcdff(v); }

// ---------------- coarse weight transform: [768][64][256] -> [768][256][64] tf32 ----
__global__ void wtrans_kernel(const float* __restrict__ src, float* __restrict__ dst)
{
    __shared__ float t[32][33];
    const int e  = blockIdx.z;
    const int p0 = blockIdx.x * 32, c0 = blockIdx.y * 32;
    const int tx = threadIdx.x, ty = threadIdx.y;   // 32 x 8
#pragma unroll
    for (int r = ty; r < 32; r += 8)
        t[r][tx] = src[((long)e*64 + c0 + r)*256 + p0 + tx];
    __syncthreads();
#pragma unroll
    for (int r = ty; r < 32; r += 8)
        dst[((long)e*256 + p0 + r)*64 + c0 + tx] = wmma::__float_to_tf32(t[tx][r]);
}

// ---------------- conv1: 3->64, 3x3, pad1, + BN + GELU (NCHW fp32) ----------------
__global__ void conv1_kernel(const float* __restrict__ x, const float* __restrict__ w,
                             const float* __restrict__ gma, const float* __restrict__ bta,
                             const float* __restrict__ mu,  const float* __restrict__ var)
{
    __shared__ float xs[3][18][18];
    __shared__ float ws[64*27];
    __shared__ float sc[64], sh[64];
    const int tid = threadIdx.y * 16 + threadIdx.x;
    const int b  = blockIdx.z;
    const int y0 = blockIdx.y * 16, x0 = blockIdx.x * 16;

    for (int i = tid; i < 3*18*18; i += 256) {
        int ci = i / 324, r = (i % 324) / 18, cc = i % 18;
        int yy = y0 - 1 + r, xx = x0 - 1 + cc;
        float v = 0.f;
        if (yy >= 0 && yy < HH && xx >= 0 && xx < HH)
            v = x[((b*3 + ci)*HH + yy)*HH + xx];
        xs[ci][r][cc] = v;
    }
    for (int i = tid; i < 64*27; i += 256) ws[i] = w[i];
    if (tid < 64) {
        float s = gma[tid] * rsqrtf(var[tid] + 1e-5f);
        sc[tid] = s; sh[tid] = bta[tid] - mu[tid] * s;
    }
    __syncthreads();

    float win[27];
#pragma unroll
    for (int ci = 0; ci < 3; ci++)
#pragma unroll
        for (int ky = 0; ky < 3; ky++)
#pragma unroll
            for (int kx = 0; kx < 3; kx++)
                win[(ci*3 + ky)*3 + kx] = xs[ci][threadIdx.y + ky][threadIdx.x + kx];

    const int y = y0 + threadIdx.y, xg = x0 + threadIdx.x;
    for (int oc = 0; oc < 64; oc++) {
        float acc = 0.f;
#pragma unroll
        for (int i = 0; i < 27; i++) acc = fmaf(ws[oc*27 + i], win[i], acc);
        float t = acc * sc[oc] + sh[oc];
        g_f1[((b*64 + oc)*HH + y)*HH + xg] = gelu_f(t);
    }
}

// ---------------- conv2: 64->64, 3x3, pad1, + BN + GELU (fp32, exact) ----------------
__global__ __launch_bounds__(256, 2)
void conv2_kernel(const float* __restrict__ w,
                  const float* __restrict__ gma, const float* __restrict__ bta,
                  const float* __restrict__ mu,  const float* __restrict__ var)
{
    __shared__ float ti[66][18];
    __shared__ float wsm[144];
    __shared__ float sc[16], sh[16];
    const int tx = threadIdx.x, ty = threadIdx.y;
    const int tid = ty * 16 + tx;
    const int bz = blockIdx.z;
    const int b = bz >> 2, ocb = (bz & 3) * 16;
    const int y0 = blockIdx.y * 64, x0 = blockIdx.x * 16;

    if (tid < 16) {
        int oc = ocb + tid;
        float s = gma[oc] * rsqrtf(var[oc] + 1e-5f);
        sc[tid] = s; sh[tid] = bta[oc] - mu[oc] * s;
    }

    float acc[4][16];
#pragma unroll
    for (int r = 0; r < 4; r++)
#pragma unroll
        for (int o = 0; o < 16; o++) acc[r][o] = 0.f;

    for (int ci = 0; ci < 64; ci++) {
        __syncthreads();
        for (int i = tid; i < 66*18; i += 256) {
            int r = i / 18, cc = i % 18;
            int yy = y0 - 1 + r, xx = x0 - 1 + cc;
            float v = 0.f;
            if (yy >= 0 && yy < HH && xx >= 0 && xx < HH)
                v = g_f1[((b*64 + ci)*HH + yy)*HH + xx];
            ti[r][cc] = v;
        }
        if (tid < 144) {
            int o = tid / 9, j = tid % 9;
            wsm[tid] = w[(ocb + o)*576 + ci*9 + j];
        }
        __syncthreads();

        float win[4][9];
#pragma unroll
        for (int r = 0; r < 4; r++)
#pragma unroll
            for (int ky = 0; ky < 3; ky++)
#pragma unroll
                for (int kx = 0; kx < 3; kx++)
                    win[r][ky*3 + kx] = ti[ty + 16*r + ky][tx + kx];

#pragma unroll
        for (int o = 0; o < 16; o++) {
#pragma unroll
            for (int j = 0; j < 9; j++) {
                float wv = wsm[o*9 + j];
#pragma unroll
                for (int r = 0; r < 4; r++)
                    acc[r][o] = fmaf(wv, win[r][j], acc[r][o]);
            }
        }
    }

#pragma unroll
    for (int r = 0; r < 4; r++) {
        int y = y0 + ty + 16*r;
#pragma unroll
        for (int o = 0; o < 16; o++) {
            float t = acc[r][o] * sc[o] + sh[o];
            g_f2[((b*64 + ocb + o)*HH + y)*HH + x0 + tx] = gelu_f(t);
        }
    }
}

// ---------------- NCHW fp32 -> NHWC tf32 transcode of f2 INTO g_f1 (overlay) ------
__global__ void transcode_kernel()
{
    __shared__ float t[64][65];
    const int b = blockIdx.z, y = blockIdx.y, x0 = blockIdx.x * 64;
    const int tx = threadIdx.x, ty = threadIdx.y;   // 64 x 4
#pragma unroll
    for (int i = 0; i < 16; i++) {
        int c = ty*16 + i;
        t[c][tx] = g_f2[((size_t)(b*64 + c)*HH + y)*HH + x0 + tx];
    }
    __syncthreads();
#pragma unroll
    for (int i = 0; i < 16; i++) {
        int r = ty*16 + i;
        g_f1[((size_t)(b*HH + y)*HH + x0 + r)*64 + tx] = wmma::__float_to_tf32(t[tx][r]);
    }
}

// ---------------- coarse GEMM: NHWC A (g_f1 overlay), tf32 B (g_cwt), no CVT ------
#define LDA 36

__global__ __launch_bounds__(256, 2)
void coarse_gemm(const float* __restrict__ W, float* __restrict__ out)
{
    constexpr int NCH = 16384 / 32;

    __shared__ __align__(16) float As[2][128*LDA];
    __shared__ __align__(16) float Bs[2][128*LDA];

    const int tid = threadIdx.x;
    const int wid = tid >> 5;
    const int bm = blockIdx.y, bn = blockIdx.x;

    const int lr = tid >> 1;
    const int half = tid & 1;
    const int arow = bm * 128 + lr;
    const int brow = bn * 128 + lr;

    int b = arow / 576; int cell = arow % 576;
    const long baseA = ((long)(b*HH + (cell/24)*16)*HH + (cell%24)*16)*64;
    const float* wp = W + (long)brow * 16384;

    const int wm = (wid & 1) * 64;
    const int wn = (wid >> 1) * 32;

    wmma::fragment<wmma::accumulator, 16, 16, 8, float> acc[4][2];
#pragma unroll
    for (int i = 0; i < 4; i++)
#pragma unroll
        for (int j = 0; j < 2; j++) wmma::fill_fragment(acc[i][j], 0.f);

    const uint32_t soff = lr*LDA + half*16;

    auto load_chunk = [&](int kc, int buf) {
#pragma unroll
        for (int j = 0; j < 4; j++) {
            const int k0 = kc + half*16 + j*4;
            int pyx = k0 >> 6, c = k0 & 63;
            const float* ap = g_f1 + baseA + ((pyx >> 4)*HH + (pyx & 15))*64 + c;
            *(float4*)&As[buf][soff + j*4] = *(const float4*)ap;
            *(float4*)&Bs[buf][soff + j*4] = *(const float4*)(wp + k0);
        }
    };

    load_chunk(0, 0);
    __syncthreads();

    for (int i = 0; i < NCH; i++) {
        const int buf = i & 1;
        if (i + 1 < NCH) load_chunk((i + 1) * 32, buf ^ 1);

#pragma unroll
        for (int ks = 0; ks < 4; ks++) {
            wmma::fragment<wmma::matrix_a, 16, 16, 8, wmma::precision::tf32, wmma::row_major> af[4];
            wmma::fragment<wmma::matrix_b, 16, 16, 8, wmma::precision::tf32, wmma::col_major> bf[2];
#pragma unroll
            for (int mi = 0; mi < 4; mi++)
                wmma::load_matrix_sync(af[mi], &As[buf][(wm + 16*mi)*LDA + ks*8], LDA);
#pragma unroll
            for (int nj = 0; nj < 2; nj++)
                wmma::load_matrix_sync(bf[nj], &Bs[buf][(wn + 16*nj)*LDA + ks*8], LDA);
#pragma unroll
            for (int mi = 0; mi < 4; mi++)
#pragma unroll
                for (int nj = 0; nj < 2; nj++)
                    wmma::mma_sync(acc[mi][nj], af[mi], bf[nj], acc[mi][nj]);
        }
        __syncthreads();
    }

#pragma unroll
    for (int mi = 0; mi < 4; mi++)
#pragma unroll
        for (int nj = 0; nj < 2; nj++) {
            long mrow = (long)bm*128 + wm + 16*mi;
            int ncol = bn*128 + wn + 16*nj;
            wmma::store_matrix_sync(&out[mrow*768 + ncol], acc[mi][nj], 768, wmma::mem_row_major);
        }
}

// ---------------- R4 GEMM (validated): MODE 1 detail@topk, MODE 2 merge ----------
template<int MODE>
__global__ __launch_bounds__(256, 2)
void wmma_gemm(const float* __restrict__ W, float* __restrict__ out)
{
    constexpr int K   = (MODE == 1) ? 4096 : 3072;
    constexpr int NCH = K / 32;

    __shared__ __align__(16) float As[2][128*LDA];
    __shared__ __align__(16) float Bs[2][128*LDA];

    const int tid = threadIdx.x;
    const int wid = tid >> 5;
    const int bm = blockIdx.y, bn = blockIdx.x;

    const int lr = tid >> 1;
    const int half = tid & 1;
    const int arow = bm * 128 + lr;
    const int brow = bn * 128 + lr;

    long baseA = 0;
    if (MODE == 1) {
        int b = arow >> 8, kk = (arow >> 2) & 63, dyx = arow & 3;
        int cell = g_topk[b*64 + kk];
        int y48 = 2*(cell/24) + (dyx >> 1);
        int x48 = 2*(cell%24) + (dyx & 1);
        baseA = ((long)(b*64)*HH + y48*8)*HH + x48*8;
    } else {
        baseA = (long)arow * 3072;
    }
    const float* wp = W + (long)brow * K;

    const int wm = (wid & 1) * 64;
    const int wn = (wid >> 1) * 32;

    wmma::fragment<wmma::accumulator, 16, 16, 8, float> acc[4][2];
#pragma unroll
    for (int i = 0; i < 4; i++)
#pragma unroll
        for (int j = 0; j < 2; j++) wmma::fill_fragment(acc[i][j], 0.f);

    const uint32_t soff = lr*LDA + half*16;

    auto load_chunk = [&](int kc, int buf) {
#pragma unroll
        for (int j = 0; j < 4; j++) {
            const int k0 = kc + half*16 + j*4;
            const float* ap;
            if (MODE == 1) {
                int c = k0 >> 6; int rem = k0 & 63;
                ap = g_f2 + baseA + (long)c*(HH*HH) + (rem >> 3)*HH + (rem & 7);
            } else {
                ap = g_dgath + baseA + k0;
            }
            float4 a = *(const float4*)ap;
            float4 b = *(const float4*)(wp + k0);
            a.x = wmma::__float_to_tf32(a.x); a.y = wmma::__float_to_tf32(a.y);
            a.z = wmma::__float_to_tf32(a.z); a.w = wmma::__float_to_tf32(a.w);
            b.x = wmma::__float_to_tf32(b.x); b.y = wmma::__float_to_tf32(b.y);
            b.z = wmma::__float_to_tf32(b.z); b.w = wmma::__float_to_tf32(b.w);
            *(float4*)&As[buf][soff + j*4] = a;
            *(float4*)&Bs[buf][soff + j*4] = b;
        }
    };

    load_chunk(0, 0);
    __syncthreads();

    for (int i = 0; i < NCH; i++) {
        const int buf = i & 1;
        if (i + 1 < NCH) load_chunk((i + 1) * 32, buf ^ 1);

#pragma unroll
        for (int ks = 0; ks < 4; ks++) {
            wmma::fragment<wmma::matrix_a, 16, 16, 8, wmma::precision::tf32, wmma::row_major> af[4];
            wmma::fragment<wmma::matrix_b, 16, 16, 8, wmma::precision::tf32, wmma::col_major> bf[2];
#pragma unroll
            for (int mi = 0; mi < 4; mi++)
                wmma::load_matrix_sync(af[mi], &As[buf][(wm + 16*mi)*LDA + ks*8], LDA);
#pragma unroll
            for (int nj = 0; nj < 2; nj++)
                wmma::load_matrix_sync(bf[nj], &Bs[buf][(wn + 16*nj)*LDA + ks*8], LDA);
#pragma unroll
            for (int mi = 0; mi < 4; mi++)
#pragma unroll
                for (int nj = 0; nj < 2; nj++)
                    wmma::mma_sync(acc[mi][nj], af[mi], bf[nj], acc[mi][nj]);
        }
        __syncthreads();
    }

    float* op = (MODE == 1) ? g_dgath : out;
#pragma unroll
    for (int mi = 0; mi < 4; mi++)
#pragma unroll
        for (int nj = 0; nj < 2; nj++) {
            long mrow = (long)bm*128 + wm + 16*mi;
            int ncol = bn*128 + wn + 16*nj;
            wmma::store_matrix_sync(&op[mrow*768 + ncol], acc[mi][nj], 768, wmma::mem_row_major);
        }
}

// ---------------- bias helpers ----------------
__global__ void add_bias_kernel(float* __restrict__ out, const float* __restrict__ bias, int n4)
{
    int i = blockIdx.x * blockDim.x + threadIdx.x;
    if (i >= n4) return;
    float4 v = ((float4*)out)[i];
    int nb = (i * 4) % 768;
    float4 b = *(const float4*)&bias[nb];
    v.x += b.x; v.y += b.y; v.z += b.z; v.w += b.w;
    ((float4*)out)[i] = v;
}

__global__ void add_mbias_kernel(float* __restrict__ out, int n4)
{
    int i = blockIdx.x * blockDim.x + threadIdx.x;
    if (i >= n4) return;
    float4 v = ((float4*)out)[i];
    int nb = (i * 4) % 768;
    float4 b = *(const float4*)&g_mbias[nb];
    v.x += b.x; v.y += b.y; v.z += b.z; v.w += b.w;
    ((float4*)out)[i] = v;
}

// g_mbias[n] = merge_b[n] + sum_k detail_b[k % 768] * merge_w[n][k]
__global__ void mbias_kernel(const float* __restrict__ merge_w, const float* __restrict__ merge_b,
                             const float* __restrict__ detail_b)
{
    const int n = blockIdx.x;
    const int tid = threadIdx.x;
    const float* wr = merge_w + (long)n * 3072;
    float s = 0.f;
    for (int k = tid; k < 3072; k += 256)
        s = fmaf(detail_b[k % 768], wr[k], s);
    __shared__ float red[256];
    red[tid] = s;
    __syncthreads();
    for (int off = 128; off > 0; off >>= 1) {
        if (tid < off) red[tid] += red[tid + off];
        __syncthreads();
    }
    if (tid == 0) g_mbias[n] = merge_b[n] + red[0];
}

// ---------------- per-patch variance score (exact fp32 NCHW) ----------------
__global__ void score_kernel()
{
    const int bi = blockIdx.x;           // b*576 + cell
    const int b = bi / 576, cell = bi % 576;
    const int gy = cell / 24, gx = cell % 24;
    const int tid = threadIdx.x;
    const int c = tid >> 2, q = tid & 3;
    const float* base = g_f2 + ((size_t)(b*64 + c)*HH + gy*16)*HH + gx*16 + q*4;
    float s = 0.f, ss = 0.f;
#pragma unroll
    for (int i = 0; i < 16; i++) {
        float4 v = *(const float4*)(base + i*HH);
        s += v.x + v.y + v.z + v.w;
        ss = fmaf(v.x, v.x, ss); ss = fmaf(v.y, v.y, ss);
        ss = fmaf(v.z, v.z, ss); ss = fmaf(v.w, v.w, ss);
    }
    s  += __shfl_down_sync(0xffffffffu, s, 2);
    s  += __shfl_down_sync(0xffffffffu, s, 1);
    ss += __shfl_down_sync(0xffffffffu, ss, 2);
    ss += __shfl_down_sync(0xffffffffu, ss, 1);
    __shared__ float cv[64];
    if ((tid & 3) == 0) {
        float mean = s * (1.f/256.f);
        cv[c] = ss * (1.f/256.f) - mean*mean;
    }
    __syncthreads();
    if (tid < 32) {
        float v = cv[tid] + cv[tid + 32];
        for (int off = 16; off > 0; off >>= 1)
            v += __shfl_down_sync(0xffffffffu, v, off);
        if (tid == 0) g_scores[bi] = v * (1.f/64.f);
    }
}

// ---------------- top-64 of 576, descending, ties -> lowest index ----------------
__global__ void topk_kernel(float* __restrict__ out_idx)
{
    const int b = blockIdx.x, tid = threadIdx.x;
    __shared__ float s[576];
    __shared__ float rv[256];
    __shared__ int   ri[256];
    for (int i = tid; i < 576; i += 256) s[i] = g_scores[b*576 + i];
    __syncthreads();
    for (int k = 0; k < 64; k++) {
        float bv = s[tid]; int bidx = tid;
        if (tid + 256 < 576) { float v = s[tid + 256]; if (v > bv) { bv = v; bidx = tid + 256; } }
        if (tid + 512 < 576) { float v = s[tid + 512]; if (v > bv) { bv = v; bidx = tid + 512; } }
        rv[tid] = bv; ri[tid] = bidx;
        __syncthreads();
        for (int off = 128; off > 0; off >>= 1) {
            if (tid < off) {
                float v2 = rv[tid + off]; int i2 = ri[tid + off];
                if (v2 > rv[tid] || (v2 == rv[tid] && i2 < ri[tid])) { rv[tid] = v2; ri[tid] = i2; }
            }
            __syncthreads();
        }
        if (tid == 0) {
            int best = ri[0];
            g_topk[b*64 + k] = best;
            out_idx[b*64 + k] = (float)best;
            s[best] = -3.0e38f;
        }
        __syncthreads();
    }
}

// ---------------- launch ----------------
extern "C" void kernel_launch(void* const* d_in, const int* in_sizes, int n_in,
                              void* d_out, int out_size)
{
    (void)in_sizes; (void)n_in; (void)out_size;
    const float* x        = (const float*)d_in[0];
    const float* conv1_w  = (const float*)d_in[1];
    const float* bn1_g    = (const float*)d_in[2];
    const float* bn1_b    = (const float*)d_in[3];
    const float* bn1_m    = (const float*)d_in[4];
    const float* bn1_v    = (const float*)d_in[5];
    const float* conv2_w  = (const float*)d_in[6];
    const float* bn2_g    = (const float*)d_in[7];
    const float* bn2_b    = (const float*)d_in[8];
    const float* bn2_m    = (const float*)d_in[9];
    const float* bn2_v    = (const float*)d_in[10];
    const float* coarse_w = (const float*)d_in[11];
    const float* coarse_b = (const float*)d_in[12];
    const float* detail_w = (const float*)d_in[13];
    const float* detail_b = (const float*)d_in[14];
    const float* merge_w  = (const float*)d_in[15];
    const float* merge_b  = (const float*)d_in[16];
    float* out = (float*)d_out;

    const long OFF1 = 16L*576*768;            // coarse tokens
    const long OFF2 = OFF1 + 16L*64*768;      // detail tokens

    // data-independent transforms
    wtrans_kernel<<<dim3(8,2,768), dim3(32,8)>>>(coarse_w, g_cwt);
    mbias_kernel<<<768, 256>>>(merge_w, merge_b, detail_b);

    // stem (fp32 exact)
    conv1_kernel<<<dim3(24,24,16), dim3(16,16)>>>(x, conv1_w, bn1_g, bn1_b, bn1_m, bn1_v);
    conv2_kernel<<<dim3(24,6,64),  dim3(16,16)>>>(conv2_w, bn2_g, bn2_b, bn2_m, bn2_v);

    // NHWC tf32 copy of f2 into g_f1 storage (g_f1 dead after conv2)
    transcode_kernel<<<dim3(6,384,16), dim3(64,4)>>>();

    // variance scores + top-k from exact fp32 f2; float idx -> out[OFF2..]
    score_kernel<<<9216, 256>>>();
    topk_kernel<<<16, 256>>>(out + OFF2);

    // coarse tokens -> out[0 .. OFF1), then += coarse_b
    coarse_gemm<<<dim3(6,72), 256>>>(g_cwt, out);
    add_bias_kernel<<<(9216*768/4 + 255)/256, 256>>>(out, coarse_b, 9216*768/4);

    // detail conv at gathered top-k positions (R4 path, NCHW f2) -> g_dgath
    wmma_gemm<1><<<dim3(6,32), 256>>>(detail_w, nullptr);

    // merge the gathered rows (R4 path) -> out[OFF1 .. OFF2), then += g_mbias
    wmma_gemm<2><<<dim3(6,8), 256>>>(merge_w, out + OFF1);
    add_mbias_kernel<<<(1024*768/4 + 255)/256, 256>>>(out + OFF1, 1024*768/4);
}

// round 11
// speedup vs baseline: 3.4742x; 3.4742x over previous
#include <cuda_runtime.h>
#include <math.h>
#include <stdint.h>
#include <mma.h>

using namespace nvcuda;

// ---------------- problem constants ----------------
#define HH 384
#define BB 16
#define CI 64
#define EE 768

// ---------------- scratch (device globals, no allocation) ----------------
__device__ float g_f1[(size_t)BB*CI*HH*HH];          // after conv1+bn+gelu
__device__ float g_f2[(size_t)BB*CI*HH*HH];          // after conv2+bn+gelu
__device__ float g_dgath[(size_t)4096*EE];           // gathered detail conv outputs (no bias)
__device__ float g_scores[BB*576];
__device__ int   g_topk[BB*64];
__device__ float g_mbias[EE];                        // effective merge bias

__device__ __forceinline__ float gelu_f(float v) { return v * normcdff(v); }

// ---------------- conv1: 3->64, 3x3, pad1, + BN + GELU ----------------
__global__ void conv1_kernel(const float* __restrict__ x, const float* __restrict__ w,
                             const float* __restrict__ gma, const float* __restrict__ bta,
                             const float* __restrict__ mu,  const float* __restrict__ var)
{
    __shared__ float xs[3][18][18];
    __shared__ float ws[64*27];
    __shared__ float sc[64], sh[64];
    const int tid = threadIdx.y * 16 + threadIdx.x;
    const int b  = blockIdx.z;
    const int y0 = blockIdx.y * 16, x0 = blockIdx.x * 16;

    for (int i = tid; i < 3*18*18; i += 256) {
        int ci = i / 324, r = (i % 324) / 18, cc = i % 18;
        int yy = y0 - 1 + r, xx = x0 - 1 + cc;
        float v = 0.f;
        if (yy >= 0 && yy < HH && xx >= 0 && xx < HH)
            v = x[((b*3 + ci)*HH + yy)*HH + xx];
        xs[ci][r][cc] = v;
    }
    for (int i = tid; i < 64*27; i += 256) ws[i] = w[i];
    if (tid < 64) {
        float s = gma[tid] * rsqrtf(var[tid] + 1e-5f);
        sc[tid] = s; sh[tid] = bta[tid] - mu[tid] * s;
    }
    __syncthreads();

    float win[27];
#pragma unroll
    for (int ci = 0; ci < 3; ci++)
#pragma unroll
        for (int ky = 0; ky < 3; ky++)
#pragma unroll
            for (int kx = 0; kx < 3; kx++)
                win[(ci*3 + ky)*3 + kx] = xs[ci][threadIdx.y + ky][threadIdx.x + kx];

    const int y = y0 + threadIdx.y, xg = x0 + threadIdx.x;
    for (int oc = 0; oc < 64; oc++) {
        float acc = 0.f;
#pragma unroll
        for (int i = 0; i < 27; i++) acc = fmaf(ws[oc*27 + i], win[i], acc);
        float t = acc * sc[oc] + sh[oc];
        g_f1[((b*64 + oc)*HH + y)*HH + xg] = gelu_f(t);
    }
}

// ---------------- conv2: 64->64, 3x3, pad1, + BN + GELU ----------------
// Same math/order as R4/R9 (f2 bit-identical). Changes: double-buffered input
// tile with register prefetch + all weights staged in smem; ONE sync per ci.
__global__ __launch_bounds__(256, 2)
void conv2_kernel(const float* __restrict__ w,
                  const float* __restrict__ gma, const float* __restrict__ bta,
                  const float* __restrict__ mu,  const float* __restrict__ var)
{
    __shared__ float ti[2][66][18];
    __shared__ float wall[16*576];     // all 64 ci x 9 taps for this block's 16 oc
    __shared__ float sc[16], sh[16];
    const int tx = threadIdx.x, ty = threadIdx.y;
    const int tid = ty * 16 + tx;
    const int bz = blockIdx.z;
    const int b = bz >> 2, ocb = (bz & 3) * 16;
    const int y0 = blockIdx.y * 64, x0 = blockIdx.x * 16;

    if (tid < 16) {
        int oc = ocb + tid;
        float s = gma[oc] * rsqrtf(var[oc] + 1e-5f);
        sc[tid] = s; sh[tid] = bta[oc] - mu[oc] * s;
    }
    // stage all weights for this oc-block: wall[o*576 + ci*9 + j]
    for (int i = tid; i < 16*576; i += 256)
        wall[i] = w[(ocb + (i / 576))*576 + (i % 576)];

    float acc[4][16];
#pragma unroll
    for (int r = 0; r < 4; r++)
#pragma unroll
        for (int o = 0; o < 16; o++) acc[r][o] = 0.f;

    // tile loader: 66*18 = 1188 elems, <=5 per thread
    auto load_tile_regs = [&](int ci, float* rg) {
#pragma unroll
        for (int k = 0; k < 5; k++) {
            int i = tid + k*256;
            float v = 0.f;
            if (i < 66*18) {
                int r = i / 18, cc = i % 18;
                int yy = y0 - 1 + r, xx = x0 - 1 + cc;
                if (yy >= 0 && yy < HH && xx >= 0 && xx < HH)
                    v = g_f1[((b*64 + ci)*HH + yy)*HH + xx];
            }
            rg[k] = v;
        }
    };
    auto store_tile = [&](int buf, const float* rg) {
#pragma unroll
        for (int k = 0; k < 5; k++) {
            int i = tid + k*256;
            if (i < 66*18) ti[buf][i / 18][i % 18] = rg[k];
        }
    };

    float rg[5];
    load_tile_regs(0, rg);
    store_tile(0, rg);
    __syncthreads();

    for (int ci = 0; ci < 64; ci++) {
        const int buf = ci & 1;
        // prefetch next tile (latency hidden under the FMA block below)
        if (ci < 63) load_tile_regs(ci + 1, rg);

        float win[4][9];
#pragma unroll
        for (int r = 0; r < 4; r++)
#pragma unroll
            for (int ky = 0; ky < 3; ky++)
#pragma unroll
                for (int kx = 0; kx < 3; kx++)
                    win[r][ky*3 + kx] = ti[buf][ty + 16*r + ky][tx + kx];

        const float* wrow = &wall[ci*9];
#pragma unroll
        for (int o = 0; o < 16; o++) {
#pragma unroll
            for (int j = 0; j < 9; j++) {
                float wv = wrow[o*576 + j];
#pragma unroll
                for (int r = 0; r < 4; r++)
                    acc[r][o] = fmaf(wv, win[r][j], acc[r][o]);
            }
        }

        if (ci < 63) {
            store_tile(buf ^ 1, rg);
            __syncthreads();
        }
    }

#pragma unroll
    for (int r = 0; r < 4; r++) {
        int y = y0 + ty + 16*r;
#pragma unroll
        for (int o = 0; o < 16; o++) {
            float t = acc[r][o] * sc[o] + sh[o];
            g_f2[((b*64 + ocb + o)*HH + y)*HH + x0 + tx] = gelu_f(t);
        }
    }
}

// ---------------- WMMA tf32 implicit GEMM: 128x128 tile, BK=32, double-buffered ----
// MODE 0: coarse  (A = 16x16 patches of f2, K=16384, M=9216) -> out
// MODE 1: detail@topk (A = 8x8 patches at gathered positions, K=4096, M=4096) -> g_dgath
// MODE 2: merge   (A = g_dgath rows, K=3072, M=1024) -> out
#define LDA 36   // padded smem leading dim (floats); 36*4=144B keeps rows 16B-aligned

template<int MODE>
__global__ __launch_bounds__(256, 2)
void wmma_gemm(const float* __restrict__ W, float* __restrict__ out)
{
    constexpr int K   = (MODE == 0) ? 16384 : ((MODE == 1) ? 4096 : 3072);
    constexpr int NCH = K / 32;

    __shared__ __align__(16) float As[2][128*LDA];
    __shared__ __align__(16) float Bs[2][128*LDA];

    const int tid = threadIdx.x;
    const int wid = tid >> 5;
    const int bm = blockIdx.y, bn = blockIdx.x;

    const int lr = tid >> 1;
    const int half = tid & 1;
    const int arow = bm * 128 + lr;
    const int brow = bn * 128 + lr;

    long baseA = 0;
    if (MODE == 0) {
        int b = arow / 576; int cell = arow % 576;
        baseA = ((long)(b*64)*HH + (cell/24)*16)*HH + (cell%24)*16;
    } else if (MODE == 1) {
        int b = arow >> 8, kk = (arow >> 2) & 63, dyx = arow & 3;
        int cell = g_topk[b*64 + kk];
        int y48 = 2*(cell/24) + (dyx >> 1);
        int x48 = 2*(cell%24) + (dyx & 1);
        baseA = ((long)(b*64)*HH + y48*8)*HH + x48*8;
    } else {
        baseA = (long)arow * 3072;
    }
    const float* wp = W + (long)brow * K;

    const int wm = (wid & 1) * 64;
    const int wn = (wid >> 1) * 32;

    wmma::fragment<wmma::accumulator, 16, 16, 8, float> acc[4][2];
#pragma unroll
    for (int i = 0; i < 4; i++)
#pragma unroll
        for (int j = 0; j < 2; j++) wmma::fill_fragment(acc[i][j], 0.f);

    const uint32_t soff = lr*LDA + half*16;

    auto load_chunk = [&](int kc, int buf) {
#pragma unroll
        for (int j = 0; j < 4; j++) {
            const int k0 = kc + half*16 + j*4;
            const float* ap;
            if (MODE == 0) {
                int c = k0 >> 8; int rem = k0 & 255;
                ap = g_f2 + baseA + (long)c*(HH*HH) + (rem >> 4)*HH + (rem & 15);
            } else if (MODE == 1) {
                int c = k0 >> 6; int rem = k0 & 63;
                ap = g_f2 + baseA + (long)c*(HH*HH) + (rem >> 3)*HH + (rem & 7);
            } else {
                ap = g_dgath + baseA + k0;
            }
            float4 a = *(const float4*)ap;
            float4 b = *(const float4*)(wp + k0);
            a.x = wmma::__float_to_tf32(a.x); a.y = wmma::__float_to_tf32(a.y);
            a.z = wmma::__float_to_tf32(a.z); a.w = wmma::__float_to_tf32(a.w);
            b.x = wmma::__float_to_tf32(b.x); b.y = wmma::__float_to_tf32(b.y);
            b.z = wmma::__float_to_tf32(b.z); b.w = wmma::__float_to_tf32(b.w);
            *(float4*)&As[buf][soff + j*4] = a;
            *(float4*)&Bs[buf][soff + j*4] = b;
        }
    };

    load_chunk(0, 0);
    __syncthreads();

    for (int i = 0; i < NCH; i++) {
        const int buf = i & 1;
        if (i + 1 < NCH) load_chunk((i + 1) * 32, buf ^ 1);

#pragma unroll
        for (int ks = 0; ks < 4; ks++) {
            wmma::fragment<wmma::matrix_a, 16, 16, 8, wmma::precision::tf32, wmma::row_major> af[4];
            wmma::fragment<wmma::matrix_b, 16, 16, 8, wmma::precision::tf32, wmma::col_major> bf[2];
#pragma unroll
            for (int mi = 0; mi < 4; mi++)
                wmma::load_matrix_sync(af[mi], &As[buf][(wm + 16*mi)*LDA + ks*8], LDA);
#pragma unroll
            for (int nj = 0; nj < 2; nj++)
                wmma::load_matrix_sync(bf[nj], &Bs[buf][(wn + 16*nj)*LDA + ks*8], LDA);
#pragma unroll
            for (int mi = 0; mi < 4; mi++)
#pragma unroll
                for (int nj = 0; nj < 2; nj++)
                    wmma::mma_sync(acc[mi][nj], af[mi], bf[nj], acc[mi][nj]);
        }
        __syncthreads();
    }

    float* op = (MODE == 1) ? g_dgath : out;
#pragma unroll
    for (int mi = 0; mi < 4; mi++)
#pragma unroll
        for (int nj = 0; nj < 2; nj++) {
            long mrow = (long)bm*128 + wm + 16*mi;
            int ncol = bn*128 + wn + 16*nj;
            wmma::store_matrix_sync(&op[mrow*768 + ncol], acc[mi][nj], 768, wmma::mem_row_major);
        }
}

// ---------------- bias helpers ----------------
__global__ void add_bias_kernel(float* __restrict__ out, const float* __restrict__ bias, int n4)
{
    int i = blockIdx.x * blockDim.x + threadIdx.x;
    if (i >= n4) return;
    float4 v = ((float4*)out)[i];
    int nb = (i * 4) % 768;
    float4 b = *(const float4*)&bias[nb];
    v.x += b.x; v.y += b.y; v.z += b.z; v.w += b.w;
    ((float4*)out)[i] = v;
}

__global__ void add_mbias_kernel(float* __restrict__ out, int n4)
{
    int i = blockIdx.x * blockDim.x + threadIdx.x;
    if (i >= n4) return;
    float4 v = ((float4*)out)[i];
    int nb = (i * 4) % 768;
    float4 b = *(const float4*)&g_mbias[nb];
    v.x += b.x; v.y += b.y; v.z += b.z; v.w += b.w;
    ((float4*)out)[i] = v;
}

// g_mbias[n] = merge_b[n] + sum_k detail_b[k % 768] * merge_w[n][k]
__global__ void mbias_kernel(const float* __restrict__ merge_w, const float* __restrict__ merge_b,
                             const float* __restrict__ detail_b)
{
    const int n = blockIdx.x;
    const int tid = threadIdx.x;
    const float* wr = merge_w + (long)n * 3072;
    float s = 0.f;
    for (int k = tid; k < 3072; k += 256)
        s = fmaf(detail_b[k % 768], wr[k], s);
    __shared__ float red[256];
    red[tid] = s;
    __syncthreads();
    for (int off = 128; off > 0; off >>= 1) {
        if (tid < off) red[tid] += red[tid + off];
        __syncthreads();
    }
    if (tid == 0) g_mbias[n] = merge_b[n] + red[0];
}

// ---------------- per-patch variance score (coalesced float4) ----------------
__global__ void score_kernel()
{
    const int bi = blockIdx.x;           // b*576 + cell
    const int b = bi / 576, cell = bi % 576;
    const int gy = cell / 24, gx = cell % 24;
    const int tid = threadIdx.x;
    const int c = tid >> 2, q = tid & 3;
    const float* base = g_f2 + ((size_t)(b*64 + c)*HH + gy*16)*HH + gx*16 + q*4;
    float s = 0.f, ss = 0.f;
#pragma unroll
    for (int i = 0; i < 16; i++) {
        float4 v = *(const float4*)(base + i*HH);
        s += v.x + v.y + v.z + v.w;
        ss = fmaf(v.x, v.x, ss); ss = fmaf(v.y, v.y, ss);
        ss = fmaf(v.z, v.z, ss); ss = fmaf(v.w, v.w, ss);
    }
    s  += __shfl_down_sync(0xffffffffu, s, 2);
    s  += __shfl_down_sync(0xffffffffu, s, 1);
    ss += __shfl_down_sync(0xffffffffu, ss, 2);
    ss += __shfl_down_sync(0xffffffffu, ss, 1);
    __shared__ float cv[64];
    if ((tid & 3) == 0) {
        float mean = s * (1.f/256.f);
        cv[c] = ss * (1.f/256.f) - mean*mean;
    }
    __syncthreads();
    if (tid < 32) {
        float v = cv[tid] + cv[tid + 32];
        for (int off = 16; off > 0; off >>= 1)
            v += __shfl_down_sync(0xffffffffu, v, off);
        if (tid == 0) g_scores[bi] = v * (1.f/64.f);
    }
}

// ---------------- top-64 of 576, descending, ties -> lowest index ----------------
__global__ void topk_kernel(float* __restrict__ out_idx)
{
    const int b = blockIdx.x, tid = threadIdx.x;
    __shared__ float s[576];
    __shared__ float rv[256];
    __shared__ int   ri[256];
    for (int i = tid; i < 576; i += 256) s[i] = g_scores[b*576 + i];
    __syncthreads();
    for (int k = 0; k < 64; k++) {
        float bv = s[tid]; int bidx = tid;
        if (tid + 256 < 576) { float v = s[tid + 256]; if (v > bv) { bv = v; bidx = tid + 256; } }
        if (tid + 512 < 576) { float v = s[tid + 512]; if (v > bv) { bv = v; bidx = tid + 512; } }
        rv[tid] = bv; ri[tid] = bidx;
        __syncthreads();
        for (int off = 128; off > 0; off >>= 1) {
            if (tid < off) {
                float v2 = rv[tid + off]; int i2 = ri[tid + off];
                if (v2 > rv[tid] || (v2 == rv[tid] && i2 < ri[tid])) { rv[tid] = v2; ri[tid] = i2; }
            }
            __syncthreads();
        }
        if (tid == 0) {
            int best = ri[0];
            g_topk[b*64 + k] = best;
            out_idx[b*64 + k] = (float)best;
            s[best] = -3.0e38f;
        }
        __syncthreads();
    }
}

// ---------------- launch ----------------
extern "C" void kernel_launch(void* const* d_in, const int* in_sizes, int n_in,
                              void* d_out, int out_size)
{
    (void)in_sizes; (void)n_in; (void)out_size;
    const float* x        = (const float*)d_in[0];
    const float* conv1_w  = (const float*)d_in[1];
    const float* bn1_g    = (const float*)d_in[2];
    const float* bn1_b    = (const float*)d_in[3];
    const float* bn1_m    = (const float*)d_in[4];
    const float* bn1_v    = (const float*)d_in[5];
    const float* conv2_w  = (const float*)d_in[6];
    const float* bn2_g    = (const float*)d_in[7];
    const float* bn2_b    = (const float*)d_in[8];
    const float* bn2_m    = (const float*)d_in[9];
    const float* bn2_v    = (const float*)d_in[10];
    const float* coarse_w = (const float*)d_in[11];
    const float* coarse_b = (const float*)d_in[12];
    const float* detail_w = (const float*)d_in[13];
    const float* detail_b = (const float*)d_in[14];
    const float* merge_w  = (const float*)d_in[15];
    const float* merge_b  = (const float*)d_in[16];
    float* out = (float*)d_out;

    const long OFF1 = 16L*576*768;            // coarse tokens
    const long OFF2 = OFF1 + 16L*64*768;      // detail tokens

    conv1_kernel<<<dim3(24,24,16), dim3(16,16)>>>(x, conv1_w, bn1_g, bn1_b, bn1_m, bn1_v);
    conv2_kernel<<<dim3(24,6,64),  dim3(16,16)>>>(conv2_w, bn2_g, bn2_b, bn2_m, bn2_v);

    // effective merge bias (independent of stem; run early)
    mbias_kernel<<<768, 256>>>(merge_w, merge_b, detail_b);

    // variance scores + top-k FIRST (they only need f2); writes float idx to out[OFF2..]
    score_kernel<<<9216, 256>>>();
    topk_kernel<<<16, 256>>>(out + OFF2);

    // coarse tokens -> out[0 .. OFF1), then += coarse_b
    wmma_gemm<0><<<dim3(6,72), 256>>>(coarse_w, out);
    add_bias_kernel<<<(9216*768/4 + 255)/256, 256>>>(out, coarse_b, 9216*768/4);

    // detail conv ONLY at gathered top-k positions -> g_dgath [4096 x 768]
    wmma_gemm<1><<<dim3(6,32), 256>>>(detail_w, nullptr);

    // merge the gathered rows -> out[OFF1 .. OFF2), then += g_mbias
    wmma_gemm<2><<<dim3(6,8), 256>>>(merge_w, out + OFF1);
    add_mbias_kernel<<<(1024*768/4 + 255)/256, 256>>>(out + OFF1, 1024*768/4);
}

// round 12
// speedup vs baseline: 4.4650x; 1.2852x over previous
#include <cuda_runtime.h>
#include <cuda_fp16.h>
#include <math.h>
#include <stdint.h>
#include <mma.h>

using namespace nvcuda;

// ---------------- problem constants ----------------
#define HH 384
#define BB 16
#define CI 64
#define EE 768

// ---------------- scratch (device globals, no allocation) ----------------
__device__ float g_f1[(size_t)BB*CI*HH*HH];          // after conv1+bn+gelu
__device__ float g_f2[(size_t)BB*CI*HH*HH];          // after conv2+bn+gelu
__device__ float g_dgath[(size_t)4096*EE];           // gathered detail conv outputs (no bias)
__device__ float g_scores[BB*576];
__device__ int   g_topk[BB*64];
__device__ float g_mbias[EE];                        // effective merge bias

__device__ __forceinline__ float gelu_f(float v) { return v * normcdff(v); }

// ---------------- conv1: 3->64, 3x3, pad1, + BN + GELU ----------------
__global__ void conv1_kernel(const float* __restrict__ x, const float* __restrict__ w,
                             const float* __restrict__ gma, const float* __restrict__ bta,
                             const float* __restrict__ mu,  const float* __restrict__ var)
{
    __shared__ float xs[3][18][18];
    __shared__ float ws[64*27];
    __shared__ float sc[64], sh[64];
    const int tid = threadIdx.y * 16 + threadIdx.x;
    const int b  = blockIdx.z;
    const int y0 = blockIdx.y * 16, x0 = blockIdx.x * 16;

    for (int i = tid; i < 3*18*18; i += 256) {
        int ci = i / 324, r = (i % 324) / 18, cc = i % 18;
        int yy = y0 - 1 + r, xx = x0 - 1 + cc;
        float v = 0.f;
        if (yy >= 0 && yy < HH && xx >= 0 && xx < HH)
            v = x[((b*3 + ci)*HH + yy)*HH + xx];
        xs[ci][r][cc] = v;
    }
    for (int i = tid; i < 64*27; i += 256) ws[i] = w[i];
    if (tid < 64) {
        float s = gma[tid] * rsqrtf(var[tid] + 1e-5f);
        sc[tid] = s; sh[tid] = bta[tid] - mu[tid] * s;
    }
    __syncthreads();

    float win[27];
#pragma unroll
    for (int ci = 0; ci < 3; ci++)
#pragma unroll
        for (int ky = 0; ky < 3; ky++)
#pragma unroll
            for (int kx = 0; kx < 3; kx++)
                win[(ci*3 + ky)*3 + kx] = xs[ci][threadIdx.y + ky][threadIdx.x + kx];

    const int y = y0 + threadIdx.y, xg = x0 + threadIdx.x;
    for (int oc = 0; oc < 64; oc++) {
        float acc = 0.f;
#pragma unroll
        for (int i = 0; i < 27; i++) acc = fmaf(ws[oc*27 + i], win[i], acc);
        float t = acc * sc[oc] + sh[oc];
        g_f1[((b*64 + oc)*HH + y)*HH + xg] = gelu_f(t);
    }
}

// ---------------- conv2: 64->64, 3x3, pad1, + BN + GELU (R11 winner) --------------
__global__ __launch_bounds__(256, 2)
void conv2_kernel(const float* __restrict__ w,
                  const float* __restrict__ gma, const float* __restrict__ bta,
                  const float* __restrict__ mu,  const float* __restrict__ var)
{
    __shared__ float ti[2][66][18];
    __shared__ float wall[16*576];
    __shared__ float sc[16], sh[16];
    const int tx = threadIdx.x, ty = threadIdx.y;
    const int tid = ty * 16 + tx;
    const int bz = blockIdx.z;
    const int b = bz >> 2, ocb = (bz & 3) * 16;
    const int y0 = blockIdx.y * 64, x0 = blockIdx.x * 16;

    if (tid < 16) {
        int oc = ocb + tid;
        float s = gma[oc] * rsqrtf(var[oc] + 1e-5f);
        sc[tid] = s; sh[tid] = bta[oc] - mu[oc] * s;
    }
    for (int i = tid; i < 16*576; i += 256)
        wall[i] = w[(ocb + (i / 576))*576 + (i % 576)];

    float acc[4][16];
#pragma unroll
    for (int r = 0; r < 4; r++)
#pragma unroll
        for (int o = 0; o < 16; o++) acc[r][o] = 0.f;

    auto load_tile_regs = [&](int ci, float* rg) {
#pragma unroll
        for (int k = 0; k < 5; k++) {
            int i = tid + k*256;
            float v = 0.f;
            if (i < 66*18) {
                int r = i / 18, cc = i % 18;
                int yy = y0 - 1 + r, xx = x0 - 1 + cc;
                if (yy >= 0 && yy < HH && xx >= 0 && xx < HH)
                    v = g_f1[((b*64 + ci)*HH + yy)*HH + xx];
            }
            rg[k] = v;
        }
    };
    auto store_tile = [&](int buf, const float* rg) {
#pragma unroll
        for (int k = 0; k < 5; k++) {
            int i = tid + k*256;
            if (i < 66*18) ti[buf][i / 18][i % 18] = rg[k];
        }
    };

    float rg[5];
    load_tile_regs(0, rg);
    store_tile(0, rg);
    __syncthreads();

    for (int ci = 0; ci < 64; ci++) {
        const int buf = ci & 1;
        if (ci < 63) load_tile_regs(ci + 1, rg);

        float win[4][9];
#pragma unroll
        for (int r = 0; r < 4; r++)
#pragma unroll
            for (int ky = 0; ky < 3; ky++)
#pragma unroll
                for (int kx = 0; kx < 3; kx++)
                    win[r][ky*3 + kx] = ti[buf][ty + 16*r + ky][tx + kx];

        const float* wrow = &wall[ci*9];
#pragma unroll
        for (int o = 0; o < 16; o++) {
#pragma unroll
            for (int j = 0; j < 9; j++) {
                float wv = wrow[o*576 + j];
#pragma unroll
                for (int r = 0; r < 4; r++)
                    acc[r][o] = fmaf(wv, win[r][j], acc[r][o]);
            }
        }

        if (ci < 63) {
            store_tile(buf ^ 1, rg);
            __syncthreads();
        }
    }

#pragma unroll
    for (int r = 0; r < 4; r++) {
        int y = y0 + ty + 16*r;
#pragma unroll
        for (int o = 0; o < 16; o++) {
            float t = acc[r][o] * sc[o] + sh[o];
            g_f2[((b*64 + ocb + o)*HH + y)*HH + x0 + tx] = gelu_f(t);
        }
    }
}

// ---------------- WMMA fp16 implicit GEMM: 128x128 tile, BK=32, double-buffered ----
// Same skeleton/addressing as the validated tf32 version; only the MMA datatype
// changed (fp16 m16n16k16, fp32 accumulate). 10-bit mantissa = same as tf32.
// MODE 0: coarse  (A = 16x16 patches of f2, K=16384, M=9216) -> out
// MODE 1: detail@topk (A = 8x8 patches at gathered positions, K=4096) -> g_dgath
// MODE 2: merge   (A = g_dgath rows, K=3072, M=1024) -> out
#define LDAH 40   // smem leading dim in halves; 40*2=80B rows, 16B-aligned

template<int MODE>
__global__ __launch_bounds__(256, 2)
void wmma_gemm(const float* __restrict__ W, float* __restrict__ out)
{
    constexpr int K   = (MODE == 0) ? 16384 : ((MODE == 1) ? 4096 : 3072);
    constexpr int NCH = K / 32;

    __shared__ __align__(16) __half As[2][128*LDAH];
    __shared__ __align__(16) __half Bs[2][128*LDAH];

    const int tid = threadIdx.x;
    const int wid = tid >> 5;
    const int bm = blockIdx.y, bn = blockIdx.x;

    const int lr = tid >> 1;          // A/B row within tile
    const int half_ = tid & 1;        // k sub-16 selector
    const int arow = bm * 128 + lr;
    const int brow = bn * 128 + lr;

    long baseA = 0;
    if (MODE == 0) {
        int b = arow / 576; int cell = arow % 576;
        baseA = ((long)(b*64)*HH + (cell/24)*16)*HH + (cell%24)*16;
    } else if (MODE == 1) {
        int b = arow >> 8, kk = (arow >> 2) & 63, dyx = arow & 3;
        int cell = g_topk[b*64 + kk];
        int y48 = 2*(cell/24) + (dyx >> 1);
        int x48 = 2*(cell%24) + (dyx & 1);
        baseA = ((long)(b*64)*HH + y48*8)*HH + x48*8;
    } else {
        baseA = (long)arow * 3072;
    }
    const float* wp = W + (long)brow * K;

    const int wm = (wid & 1) * 64;
    const int wn = (wid >> 1) * 32;

    wmma::fragment<wmma::accumulator, 16, 16, 16, float> acc[4][2];
#pragma unroll
    for (int i = 0; i < 4; i++)
#pragma unroll
        for (int j = 0; j < 2; j++) wmma::fill_fragment(acc[i][j], 0.f);

    const uint32_t soff = lr*LDAH + half_*16;   // in halves; byte-align 16 OK

    auto load_chunk = [&](int kc, int buf) {
        uint32_t pa[8], pb[8];
#pragma unroll
        for (int j = 0; j < 4; j++) {
            const int k0 = kc + half_*16 + j*4;
            const float* ap;
            if (MODE == 0) {
                int c = k0 >> 8; int rem = k0 & 255;
                ap = g_f2 + baseA + (long)c*(HH*HH) + (rem >> 4)*HH + (rem & 15);
            } else if (MODE == 1) {
                int c = k0 >> 6; int rem = k0 & 63;
                ap = g_f2 + baseA + (long)c*(HH*HH) + (rem >> 3)*HH + (rem & 7);
            } else {
                ap = g_dgath + baseA + k0;
            }
            float4 a = *(const float4*)ap;
            float4 b = *(const float4*)(wp + k0);
            __half2 a01 = __floats2half2_rn(a.x, a.y);
            __half2 a23 = __floats2half2_rn(a.z, a.w);
            __half2 b01 = __floats2half2_rn(b.x, b.y);
            __half2 b23 = __floats2half2_rn(b.z, b.w);
            pa[2*j]   = *(uint32_t*)&a01; pa[2*j+1] = *(uint32_t*)&a23;
            pb[2*j]   = *(uint32_t*)&b01; pb[2*j+1] = *(uint32_t*)&b23;
        }
        *(uint4*)&As[buf][soff]     = make_uint4(pa[0], pa[1], pa[2], pa[3]);
        *(uint4*)&As[buf][soff + 8] = make_uint4(pa[4], pa[5], pa[6], pa[7]);
        *(uint4*)&Bs[buf][soff]     = make_uint4(pb[0], pb[1], pb[2], pb[3]);
        *(uint4*)&Bs[buf][soff + 8] = make_uint4(pb[4], pb[5], pb[6], pb[7]);
    };

    load_chunk(0, 0);
    __syncthreads();

    for (int i = 0; i < NCH; i++) {
        const int buf = i & 1;
        if (i + 1 < NCH) load_chunk((i + 1) * 32, buf ^ 1);

#pragma unroll
        for (int ks = 0; ks < 2; ks++) {
            wmma::fragment<wmma::matrix_a, 16, 16, 16, half, wmma::row_major> af[4];
            wmma::fragment<wmma::matrix_b, 16, 16, 16, half, wmma::col_major> bf[2];
#pragma unroll
            for (int mi = 0; mi < 4; mi++)
                wmma::load_matrix_sync(af[mi], &As[buf][(wm + 16*mi)*LDAH + ks*16], LDAH);
#pragma unroll
            for (int nj = 0; nj < 2; nj++)
                wmma::load_matrix_sync(bf[nj], &Bs[buf][(wn + 16*nj)*LDAH + ks*16], LDAH);
#pragma unroll
            for (int mi = 0; mi < 4; mi++)
#pragma unroll
                for (int nj = 0; nj < 2; nj++)
                    wmma::mma_sync(acc[mi][nj], af[mi], bf[nj], acc[mi][nj]);
        }
        __syncthreads();
    }

    float* op = (MODE == 1) ? g_dgath : out;
#pragma unroll
    for (int mi = 0; mi < 4; mi++)
#pragma unroll
        for (int nj = 0; nj < 2; nj++) {
            long mrow = (long)bm*128 + wm + 16*mi;
            int ncol = bn*128 + wn + 16*nj;
            wmma::store_matrix_sync(&op[mrow*768 + ncol], acc[mi][nj], 768, wmma::mem_row_major);
        }
}

// ---------------- bias helpers ----------------
__global__ void add_bias_kernel(float* __restrict__ out, const float* __restrict__ bias, int n4)
{
    int i = blockIdx.x * blockDim.x + threadIdx.x;
    if (i >= n4) return;
    float4 v = ((float4*)out)[i];
    int nb = (i * 4) % 768;
    float4 b = *(const float4*)&bias[nb];
    v.x += b.x; v.y += b.y; v.z += b.z; v.w += b.w;
    ((float4*)out)[i] = v;
}

__global__ void add_mbias_kernel(float* __restrict__ out, int n4)
{
    int i = blockIdx.x * blockDim.x + threadIdx.x;
    if (i >= n4) return;
    float4 v = ((float4*)out)[i];
    int nb = (i * 4) % 768;
    float4 b = *(const float4*)&g_mbias[nb];
    v.x += b.x; v.y += b.y; v.z += b.z; v.w += b.w;
    ((float4*)out)[i] = v;
}

// g_mbias[n] = merge_b[n] + sum_k detail_b[k % 768] * merge_w[n][k]
__global__ void mbias_kernel(const float* __restrict__ merge_w, const float* __restrict__ merge_b,
                             const float* __restrict__ detail_b)
{
    const int n = blockIdx.x;
    const int tid = threadIdx.x;
    const float* wr = merge_w + (long)n * 3072;
    float s = 0.f;
    for (int k = tid; k < 3072; k += 256)
        s = fmaf(detail_b[k % 768], wr[k], s);
    __shared__ float red[256];
    red[tid] = s;
    __syncthreads();
    for (int off = 128; off > 0; off >>= 1) {
        if (tid < off) red[tid] += red[tid + off];
        __syncthreads();
    }
    if (tid == 0) g_mbias[n] = merge_b[n] + red[0];
}

// ---------------- per-patch variance score (exact fp32 NCHW) ----------------
__global__ void score_kernel()
{
    const int bi = blockIdx.x;           // b*576 + cell
    const int b = bi / 576, cell = bi % 576;
    const int gy = cell / 24, gx = cell % 24;
    const int tid = threadIdx.x;
    const int c = tid >> 2, q = tid & 3;
    const float* base = g_f2 + ((size_t)(b*64 + c)*HH + gy*16)*HH + gx*16 + q*4;
    float s = 0.f, ss = 0.f;
#pragma unroll
    for (int i = 0; i < 16; i++) {
        float4 v = *(const float4*)(base + i*HH);
        s += v.x + v.y + v.z + v.w;
        ss = fmaf(v.x, v.x, ss); ss = fmaf(v.y, v.y, ss);
        ss = fmaf(v.z, v.z, ss); ss = fmaf(v.w, v.w, ss);
    }
    s  += __shfl_down_sync(0xffffffffu, s, 2);
    s  += __shfl_down_sync(0xffffffffu, s, 1);
    ss += __shfl_down_sync(0xffffffffu, ss, 2);
    ss += __shfl_down_sync(0xffffffffu, ss, 1);
    __shared__ float cv[64];
    if ((tid & 3) == 0) {
        float mean = s * (1.f/256.f);
        cv[c] = ss * (1.f/256.f) - mean*mean;
    }
    __syncthreads();
    if (tid < 32) {
        float v = cv[tid] + cv[tid + 32];
        for (int off = 16; off > 0; off >>= 1)
            v += __shfl_down_sync(0xffffffffu, v, off);
        if (tid == 0) g_scores[bi] = v * (1.f/64.f);
    }
}

// ---------------- top-64 of 576, descending, ties -> lowest index ----------------
__global__ void topk_kernel(float* __restrict__ out_idx)
{
    const int b = blockIdx.x, tid = threadIdx.x;
    __shared__ float s[576];
    __shared__ float rv[256];
    __shared__ int   ri[256];
    for (int i = tid; i < 576; i += 256) s[i] = g_scores[b*576 + i];
    __syncthreads();
    for (int k = 0; k < 64; k++) {
        float bv = s[tid]; int bidx = tid;
        if (tid + 256 < 576) { float v = s[tid + 256]; if (v > bv) { bv = v; bidx = tid + 256; } }
        if (tid + 512 < 576) { float v = s[tid + 512]; if (v > bv) { bv = v; bidx = tid + 512; } }
        rv[tid] = bv; ri[tid] = bidx;
        __syncthreads();
        for (int off = 128; off > 0; off >>= 1) {
            if (tid < off) {
                float v2 = rv[tid + off]; int i2 = ri[tid + off];
                if (v2 > rv[tid] || (v2 == rv[tid] && i2 < ri[tid])) { rv[tid] = v2; ri[tid] = i2; }
            }
            __syncthreads();
        }
        if (tid == 0) {
            int best = ri[0];
            g_topk[b*64 + k] = best;
            out_idx[b*64 + k] = (float)best;
            s[best] = -3.0e38f;
        }
        __syncthreads();
    }
}

// ---------------- launch ----------------
extern "C" void kernel_launch(void* const* d_in, const int* in_sizes, int n_in,
                              void* d_out, int out_size)
{
    (void)in_sizes; (void)n_in; (void)out_size;
    const float* x        = (const float*)d_in[0];
    const float* conv1_w  = (const float*)d_in[1];
    const float* bn1_g    = (const float*)d_in[2];
    const float* bn1_b    = (const float*)d_in[3];
    const float* bn1_m    = (const float*)d_in[4];
    const float* bn1_v    = (const float*)d_in[5];
    const float* conv2_w  = (const float*)d_in[6];
    const float* bn2_g    = (const float*)d_in[7];
    const float* bn2_b    = (const float*)d_in[8];
    const float* bn2_m    = (const float*)d_in[9];
    const float* bn2_v    = (const float*)d_in[10];
    const float* coarse_w = (const float*)d_in[11];
    const float* coarse_b = (const float*)d_in[12];
    const float* detail_w = (const float*)d_in[13];
    const float* detail_b = (const float*)d_in[14];
    const float* merge_w  = (const float*)d_in[15];
    const float* merge_b  = (const float*)d_in[16];
    float* out = (float*)d_out;

    const long OFF1 = 16L*576*768;            // coarse tokens
    const long OFF2 = OFF1 + 16L*64*768;      // detail tokens

    conv1_kernel<<<dim3(24,24,16), dim3(16,16)>>>(x, conv1_w, bn1_g, bn1_b, bn1_m, bn1_v);
    conv2_kernel<<<dim3(24,6,64),  dim3(16,16)>>>(conv2_w, bn2_g, bn2_b, bn2_m, bn2_v);

    // effective merge bias (independent of stem; run early)
    mbias_kernel<<<768, 256>>>(merge_w, merge_b, detail_b);

    // variance scores + top-k FIRST (they only need f2); writes float idx to out[OFF2..]
    score_kernel<<<9216, 256>>>();
    topk_kernel<<<16, 256>>>(out + OFF2);

    // coarse tokens -> out[0 .. OFF1), then += coarse_b
    wmma_gemm<0><<<dim3(6,72), 256>>>(coarse_w, out);
    add_bias_kernel<<<(9216*768/4 + 255)/256, 256>>>(out, coarse_b, 9216*768/4);

    // detail conv ONLY at gathered top-k positions -> g_dgath [4096 x 768]
    wmma_gemm<1><<<dim3(6,32), 256>>>(detail_w, nullptr);

    // merge the gathered rows -> out[OFF1 .. OFF2), then += g_mbias
    wmma_gemm<2><<<dim3(6,8), 256>>>(merge_w, out + OFF1);
    add_mbias_kernel<<<(1024*768/4 + 255)/256, 256>>>(out + OFF1, 1024*768/4);
}

// round 13
// speedup vs baseline: 4.4748x; 1.0022x over previous
#include <cuda_runtime.h>
#include <cuda_fp16.h>
#include <math.h>
#include <stdint.h>
#include <mma.h>

using namespace nvcuda;

// ---------------- problem constants ----------------
#define HH 384
#define BB 16
#define CI 64
#define EE 768

// ---------------- scratch (device globals, no allocation) ----------------
__device__ float g_f1[(size_t)BB*CI*HH*HH];          // after conv1+bn+gelu
__device__ float g_f2[(size_t)BB*CI*HH*HH];          // after conv2+bn+gelu
__device__ float g_dgath[(size_t)4096*EE];           // gathered detail conv outputs (no bias)
__device__ float g_scores[BB*576];
__device__ int   g_topk[BB*64];
__device__ float g_mbias[EE];                        // effective merge bias

__device__ __forceinline__ float gelu_f(float v) { return v * normcdff(v); }

// ---------------- conv1: 3->64, 3x3, pad1, + BN + GELU ----------------
__global__ void conv1_kernel(const float* __restrict__ x, const float* __restrict__ w,
                             const float* __restrict__ gma, const float* __restrict__ bta,
                             const float* __restrict__ mu,  const float* __restrict__ var)
{
    __shared__ float xs[3][18][18];
    __shared__ float ws[64*27];
    __shared__ float sc[64], sh[64];
    const int tid = threadIdx.y * 16 + threadIdx.x;
    const int b  = blockIdx.z;
    const int y0 = blockIdx.y * 16, x0 = blockIdx.x * 16;

    for (int i = tid; i < 3*18*18; i += 256) {
        int ci = i / 324, r = (i % 324) / 18, cc = i % 18;
        int yy = y0 - 1 + r, xx = x0 - 1 + cc;
        float v = 0.f;
        if (yy >= 0 && yy < HH && xx >= 0 && xx < HH)
            v = x[((b*3 + ci)*HH + yy)*HH + xx];
        xs[ci][r][cc] = v;
    }
    for (int i = tid; i < 64*27; i += 256) ws[i] = w[i];
    if (tid < 64) {
        float s = gma[tid] * rsqrtf(var[tid] + 1e-5f);
        sc[tid] = s; sh[tid] = bta[tid] - mu[tid] * s;
    }
    __syncthreads();

    float win[27];
#pragma unroll
    for (int ci = 0; ci < 3; ci++)
#pragma unroll
        for (int ky = 0; ky < 3; ky++)
#pragma unroll
            for (int kx = 0; kx < 3; kx++)
                win[(ci*3 + ky)*3 + kx] = xs[ci][threadIdx.y + ky][threadIdx.x + kx];

    const int y = y0 + threadIdx.y, xg = x0 + threadIdx.x;
    for (int oc = 0; oc < 64; oc++) {
        float acc = 0.f;
#pragma unroll
        for (int i = 0; i < 27; i++) acc = fmaf(ws[oc*27 + i], win[i], acc);
        float t = acc * sc[oc] + sh[oc];
        g_f1[((b*64 + oc)*HH + y)*HH + xg] = gelu_f(t);
    }
}

// ---------------- conv2: 64->64, 3x3, pad1, + BN + GELU (R11 winner) --------------
__global__ __launch_bounds__(256, 2)
void conv2_kernel(const float* __restrict__ w,
                  const float* __restrict__ gma, const float* __restrict__ bta,
                  const float* __restrict__ mu,  const float* __restrict__ var)
{
    __shared__ float ti[2][66][18];
    __shared__ float wall[16*576];
    __shared__ float sc[16], sh[16];
    const int tx = threadIdx.x, ty = threadIdx.y;
    const int tid = ty * 16 + tx;
    const int bz = blockIdx.z;
    const int b = bz >> 2, ocb = (bz & 3) * 16;
    const int y0 = blockIdx.y * 64, x0 = blockIdx.x * 16;

    if (tid < 16) {
        int oc = ocb + tid;
        float s = gma[oc] * rsqrtf(var[oc] + 1e-5f);
        sc[tid] = s; sh[tid] = bta[oc] - mu[oc] * s;
    }
    for (int i = tid; i < 16*576; i += 256)
        wall[i] = w[(ocb + (i / 576))*576 + (i % 576)];

    float acc[4][16];
#pragma unroll
    for (int r = 0; r < 4; r++)
#pragma unroll
        for (int o = 0; o < 16; o++) acc[r][o] = 0.f;

    auto load_tile_regs = [&](int ci, float* rg) {
#pragma unroll
        for (int k = 0; k < 5; k++) {
            int i = tid + k*256;
            float v = 0.f;
            if (i < 66*18) {
                int r = i / 18, cc = i % 18;
                int yy = y0 - 1 + r, xx = x0 - 1 + cc;
                if (yy >= 0 && yy < HH && xx >= 0 && xx < HH)
                    v = g_f1[((b*64 + ci)*HH + yy)*HH + xx];
            }
            rg[k] = v;
        }
    };
    auto store_tile = [&](int buf, const float* rg) {
#pragma unroll
        for (int k = 0; k < 5; k++) {
            int i = tid + k*256;
            if (i < 66*18) ti[buf][i / 18][i % 18] = rg[k];
        }
    };

    float rg[5];
    load_tile_regs(0, rg);
    store_tile(0, rg);
    __syncthreads();

    for (int ci = 0; ci < 64; ci++) {
        const int buf = ci & 1;
        if (ci < 63) load_tile_regs(ci + 1, rg);

        float win[4][9];
#pragma unroll
        for (int r = 0; r < 4; r++)
#pragma unroll
            for (int ky = 0; ky < 3; ky++)
#pragma unroll
                for (int kx = 0; kx < 3; kx++)
                    win[r][ky*3 + kx] = ti[buf][ty + 16*r + ky][tx + kx];

        const float* wrow = &wall[ci*9];
#pragma unroll
        for (int o = 0; o < 16; o++) {
#pragma unroll
            for (int j = 0; j < 9; j++) {
                float wv = wrow[o*576 + j];
#pragma unroll
                for (int r = 0; r < 4; r++)
                    acc[r][o] = fmaf(wv, win[r][j], acc[r][o]);
            }
        }

        if (ci < 63) {
            store_tile(buf ^ 1, rg);
            __syncthreads();
        }
    }

#pragma unroll
    for (int r = 0; r < 4; r++) {
        int y = y0 + ty + 16*r;
#pragma unroll
        for (int o = 0; o < 16; o++) {
            float t = acc[r][o] * sc[o] + sh[o];
            g_f2[((b*64 + ocb + o)*HH + y)*HH + x0 + tx] = gelu_f(t);
        }
    }
}

// ---------------- WMMA fp16 implicit GEMM: 128x128 tile, BK=64, double-buffered ----
// R12 skeleton with BK 32 -> 64 (half the barriers, 2x MMA per sync).
// MODE 0: coarse  (A = 16x16 patches of f2, K=16384, M=9216) -> out
// MODE 1: detail@topk (A = 8x8 patches at gathered positions, K=4096) -> g_dgath
// MODE 2: merge   (A = g_dgath rows, K=3072, M=1024) -> out
#define LDAH 72   // smem leading dim in halves; 72*2=144B rows, 16B-aligned

template<int MODE>
__global__ __launch_bounds__(256, 2)
void wmma_gemm(const float* __restrict__ W, float* __restrict__ out)
{
    constexpr int K   = (MODE == 0) ? 16384 : ((MODE == 1) ? 4096 : 3072);
    constexpr int NCH = K / 64;

    __shared__ __align__(16) __half As[2][128*LDAH];
    __shared__ __align__(16) __half Bs[2][128*LDAH];

    const int tid = threadIdx.x;
    const int wid = tid >> 5;
    const int bm = blockIdx.y, bn = blockIdx.x;

    const int lr = tid >> 1;          // A/B row within tile
    const int kq = (tid & 1) * 32;    // k sub-32 selector
    const int arow = bm * 128 + lr;
    const int brow = bn * 128 + lr;

    long baseA = 0;
    if (MODE == 0) {
        int b = arow / 576; int cell = arow % 576;
        baseA = ((long)(b*64)*HH + (cell/24)*16)*HH + (cell%24)*16;
    } else if (MODE == 1) {
        int b = arow >> 8, kk = (arow >> 2) & 63, dyx = arow & 3;
        int cell = g_topk[b*64 + kk];
        int y48 = 2*(cell/24) + (dyx >> 1);
        int x48 = 2*(cell%24) + (dyx & 1);
        baseA = ((long)(b*64)*HH + y48*8)*HH + x48*8;
    } else {
        baseA = (long)arow * 3072;
    }
    const float* wp = W + (long)brow * K;

    const int wm = (wid & 1) * 64;
    const int wn = (wid >> 1) * 32;

    wmma::fragment<wmma::accumulator, 16, 16, 16, float> acc[4][2];
#pragma unroll
    for (int i = 0; i < 4; i++)
#pragma unroll
        for (int j = 0; j < 2; j++) wmma::fill_fragment(acc[i][j], 0.f);

    const uint32_t soff = lr*LDAH + kq;   // in halves

    auto load_chunk = [&](int kc, int buf) {
        uint32_t pa[16], pb[16];
#pragma unroll
        for (int j = 0; j < 8; j++) {
            const int k0 = kc + kq + j*4;
            const float* ap;
            if (MODE == 0) {
                int c = k0 >> 8; int rem = k0 & 255;
                ap = g_f2 + baseA + (long)c*(HH*HH) + (rem >> 4)*HH + (rem & 15);
            } else if (MODE == 1) {
                int c = k0 >> 6; int rem = k0 & 63;
                ap = g_f2 + baseA + (long)c*(HH*HH) + (rem >> 3)*HH + (rem & 7);
            } else {
                ap = g_dgath + baseA + k0;
            }
            float4 a = *(const float4*)ap;
            float4 b = *(const float4*)(wp + k0);
            __half2 a01 = __floats2half2_rn(a.x, a.y);
            __half2 a23 = __floats2half2_rn(a.z, a.w);
            __half2 b01 = __floats2half2_rn(b.x, b.y);
            __half2 b23 = __floats2half2_rn(b.z, b.w);
            pa[2*j]   = *(uint32_t*)&a01; pa[2*j+1] = *(uint32_t*)&a23;
            pb[2*j]   = *(uint32_t*)&b01; pb[2*j+1] = *(uint32_t*)&b23;
        }
#pragma unroll
        for (int q = 0; q < 4; q++) {
            *(uint4*)&As[buf][soff + q*8] = make_uint4(pa[4*q], pa[4*q+1], pa[4*q+2], pa[4*q+3]);
            *(uint4*)&Bs[buf][soff + q*8] = make_uint4(pb[4*q], pb[4*q+1], pb[4*q+2], pb[4*q+3]);
        }
    };

    load_chunk(0, 0);
    __syncthreads();

    for (int i = 0; i < NCH; i++) {
        const int buf = i & 1;
        if (i + 1 < NCH) load_chunk((i + 1) * 64, buf ^ 1);

#pragma unroll
        for (int ks = 0; ks < 4; ks++) {
            wmma::fragment<wmma::matrix_a, 16, 16, 16, half, wmma::row_major> af[4];
            wmma::fragment<wmma::matrix_b, 16, 16, 16, half, wmma::col_major> bf[2];
#pragma unroll
            for (int mi = 0; mi < 4; mi++)
                wmma::load_matrix_sync(af[mi], &As[buf][(wm + 16*mi)*LDAH + ks*16], LDAH);
#pragma unroll
            for (int nj = 0; nj < 2; nj++)
                wmma::load_matrix_sync(bf[nj], &Bs[buf][(wn + 16*nj)*LDAH + ks*16], LDAH);
#pragma unroll
            for (int mi = 0; mi < 4; mi++)
#pragma unroll
                for (int nj = 0; nj < 2; nj++)
                    wmma::mma_sync(acc[mi][nj], af[mi], bf[nj], acc[mi][nj]);
        }
        __syncthreads();
    }

    float* op = (MODE == 1) ? g_dgath : out;
#pragma unroll
    for (int mi = 0; mi < 4; mi++)
#pragma unroll
        for (int nj = 0; nj < 2; nj++) {
            long mrow = (long)bm*128 + wm + 16*mi;
            int ncol = bn*128 + wn + 16*nj;
            wmma::store_matrix_sync(&op[mrow*768 + ncol], acc[mi][nj], 768, wmma::mem_row_major);
        }
}

// ---------------- bias helpers ----------------
__global__ void add_bias_kernel(float* __restrict__ out, const float* __restrict__ bias, int n4)
{
    int i = blockIdx.x * blockDim.x + threadIdx.x;
    if (i >= n4) return;
    float4 v = ((float4*)out)[i];
    int nb = (i * 4) % 768;
    float4 b = *(const float4*)&bias[nb];
    v.x += b.x; v.y += b.y; v.z += b.z; v.w += b.w;
    ((float4*)out)[i] = v;
}

__global__ void add_mbias_kernel(float* __restrict__ out, int n4)
{
    int i = blockIdx.x * blockDim.x + threadIdx.x;
    if (i >= n4) return;
    float4 v = ((float4*)out)[i];
    int nb = (i * 4) % 768;
    float4 b = *(const float4*)&g_mbias[nb];
    v.x += b.x; v.y += b.y; v.z += b.z; v.w += b.w;
    ((float4*)out)[i] = v;
}

// g_mbias[n] = merge_b[n] + sum_k detail_b[k % 768] * merge_w[n][k]
__global__ void mbias_kernel(const float* __restrict__ merge_w, const float* __restrict__ merge_b,
                             const float* __restrict__ detail_b)
{
    const int n = blockIdx.x;
    const int tid = threadIdx.x;
    const float* wr = merge_w + (long)n * 3072;
    float s = 0.f;
    for (int k = tid; k < 3072; k += 256)
        s = fmaf(detail_b[k % 768], wr[k], s);
    __shared__ float red[256];
    red[tid] = s;
    __syncthreads();
    for (int off = 128; off > 0; off >>= 1) {
        if (tid < off) red[tid] += red[tid + off];
        __syncthreads();
    }
    if (tid == 0) g_mbias[n] = merge_b[n] + red[0];
}

// ---------------- per-patch variance score (exact fp32 NCHW) ----------------
__global__ void score_kernel()
{
    const int bi = blockIdx.x;           // b*576 + cell
    const int b = bi / 576, cell = bi % 576;
    const int gy = cell / 24, gx = cell % 24;
    const int tid = threadIdx.x;
    const int c = tid >> 2, q = tid & 3;
    const float* base = g_f2 + ((size_t)(b*64 + c)*HH + gy*16)*HH + gx*16 + q*4;
    float s = 0.f, ss = 0.f;
#pragma unroll
    for (int i = 0; i < 16; i++) {
        float4 v = *(const float4*)(base + i*HH);
        s += v.x + v.y + v.z + v.w;
        ss = fmaf(v.x, v.x, ss); ss = fmaf(v.y, v.y, ss);
        ss = fmaf(v.z, v.z, ss); ss = fmaf(v.w, v.w, ss);
    }
    s  += __shfl_down_sync(0xffffffffu, s, 2);
    s  += __shfl_down_sync(0xffffffffu, s, 1);
    ss += __shfl_down_sync(0xffffffffu, ss, 2);
    ss += __shfl_down_sync(0xffffffffu, ss, 1);
    __shared__ float cv[64];
    if ((tid & 3) == 0) {
        float mean = s * (1.f/256.f);
        cv[c] = ss * (1.f/256.f) - mean*mean;
    }
    __syncthreads();
    if (tid < 32) {
        float v = cv[tid] + cv[tid + 32];
        for (int off = 16; off > 0; off >>= 1)
            v += __shfl_down_sync(0xffffffffu, v, off);
        if (tid == 0) g_scores[bi] = v * (1.f/64.f);
    }
}

// ---------------- top-64 of 576, descending, ties -> lowest index ----------------
__global__ void topk_kernel(float* __restrict__ out_idx)
{
    const int b = blockIdx.x, tid = threadIdx.x;
    __shared__ float s[576];
    __shared__ float rv[256];
    __shared__ int   ri[256];
    for (int i = tid; i < 576; i += 256) s[i] = g_scores[b*576 + i];
    __syncthreads();
    for (int k = 0; k < 64; k++) {
        float bv = s[tid]; int bidx = tid;
        if (tid + 256 < 576) { float v = s[tid + 256]; if (v > bv) { bv = v; bidx = tid + 256; } }
        if (tid + 512 < 576) { float v = s[tid + 512]; if (v > bv) { bv = v; bidx = tid + 512; } }
        rv[tid] = bv; ri[tid] = bidx;
        __syncthreads();
        for (int off = 128; off > 0; off >>= 1) {
            if (tid < off) {
                float v2 = rv[tid + off]; int i2 = ri[tid + off];
                if (v2 > rv[tid] || (v2 == rv[tid] && i2 < ri[tid])) { rv[tid] = v2; ri[tid] = i2; }
            }
            __syncthreads();
        }
        if (tid == 0) {
            int best = ri[0];
            g_topk[b*64 + k] = best;
            out_idx[b*64 + k] = (float)best;
            s[best] = -3.0e38f;
        }
        __syncthreads();
    }
}

// ---------------- launch ----------------
extern "C" void kernel_launch(void* const* d_in, const int* in_sizes, int n_in,
                              void* d_out, int out_size)
{
    (void)in_sizes; (void)n_in; (void)out_size;
    const float* x        = (const float*)d_in[0];
    const float* conv1_w  = (const float*)d_in[1];
    const float* bn1_g    = (const float*)d_in[2];
    const float* bn1_b    = (const float*)d_in[3];
    const float* bn1_m    = (const float*)d_in[4];
    const float* bn1_v    = (const float*)d_in[5];
    const float* conv2_w  = (const float*)d_in[6];
    const float* bn2_g    = (const float*)d_in[7];
    const float* bn2_b    = (const float*)d_in[8];
    const float* bn2_m    = (const float*)d_in[9];
    const float* bn2_v    = (const float*)d_in[10];
    const float* coarse_w = (const float*)d_in[11];
    const float* coarse_b = (const float*)d_in[12];
    const float* detail_w = (const float*)d_in[13];
    const float* detail_b = (const float*)d_in[14];
    const float* merge_w  = (const float*)d_in[15];
    const float* merge_b  = (const float*)d_in[16];
    float* out = (float*)d_out;

    const long OFF1 = 16L*576*768;            // coarse tokens
    const long OFF2 = OFF1 + 16L*64*768;      // detail tokens

    // launch order arranged so the coarse GEMM is launch #4 (ncu capture slot)
    conv1_kernel<<<dim3(24,24,16), dim3(16,16)>>>(x, conv1_w, bn1_g, bn1_b, bn1_m, bn1_v);   // 1
    conv2_kernel<<<dim3(24,6,64),  dim3(16,16)>>>(conv2_w, bn2_g, bn2_b, bn2_m, bn2_v);      // 2

    score_kernel<<<9216, 256>>>();                                                           // 3
    wmma_gemm<0><<<dim3(6,72), 256>>>(coarse_w, out);                                        // 4
    topk_kernel<<<16, 256>>>(out + OFF2);                                                    // 5
    mbias_kernel<<<768, 256>>>(merge_w, merge_b, detail_b);                                  // 6

    // detail conv ONLY at gathered top-k positions -> g_dgath [4096 x 768]
    wmma_gemm<1><<<dim3(6,32), 256>>>(detail_w, nullptr);                                    // 7
    // merge the gathered rows -> out[OFF1 .. OFF2), then += g_mbias
    wmma_gemm<2><<<dim3(6,8), 256>>>(merge_w, out + OFF1);                                   // 8

    add_bias_kernel<<<(9216*768/4 + 255)/256, 256>>>(out, coarse_b, 9216*768/4);             // 9
    add_mbias_kernel<<<(1024*768/4 + 255)/256, 256>>>(out + OFF1, 1024*768/4);               // 10
}

// round 14
// speedup vs baseline: 4.5371x; 1.0139x over previous
#include <cuda_runtime.h>
#include <cuda_fp16.h>
#include <math.h>
#include <stdint.h>
#include <mma.h>

using namespace nvcuda;

// ---------------- problem constants ----------------
#define HH 384
#define BB 16
#define CI 64
#define EE 768

// ---------------- scratch (device globals, no allocation) ----------------
__device__ float g_f1[(size_t)BB*CI*HH*HH];          // after conv1+bn+gelu
__device__ float g_f2[(size_t)BB*CI*HH*HH];          // after conv2+bn+gelu
__device__ float g_part[2][(size_t)9216*EE];         // coarse split-K partials
__device__ float g_dgath[(size_t)4096*EE];           // gathered detail conv outputs (no bias)
__device__ float g_scores[BB*576];
__device__ int   g_topk[BB*64];
__device__ float g_mbias[EE];                        // effective merge bias

__device__ __forceinline__ float gelu_f(float v) { return v * normcdff(v); }

// ---------------- conv1: 3->64, 3x3, pad1, + BN + GELU ----------------
__global__ void conv1_kernel(const float* __restrict__ x, const float* __restrict__ w,
                             const float* __restrict__ gma, const float* __restrict__ bta,
                             const float* __restrict__ mu,  const float* __restrict__ var)
{
    __shared__ float xs[3][18][18];
    __shared__ float ws[64*27];
    __shared__ float sc[64], sh[64];
    const int tid = threadIdx.y * 16 + threadIdx.x;
    const int b  = blockIdx.z;
    const int y0 = blockIdx.y * 16, x0 = blockIdx.x * 16;

    for (int i = tid; i < 3*18*18; i += 256) {
        int ci = i / 324, r = (i % 324) / 18, cc = i % 18;
        int yy = y0 - 1 + r, xx = x0 - 1 + cc;
        float v = 0.f;
        if (yy >= 0 && yy < HH && xx >= 0 && xx < HH)
            v = x[((b*3 + ci)*HH + yy)*HH + xx];
        xs[ci][r][cc] = v;
    }
    for (int i = tid; i < 64*27; i += 256) ws[i] = w[i];
    if (tid < 64) {
        float s = gma[tid] * rsqrtf(var[tid] + 1e-5f);
        sc[tid] = s; sh[tid] = bta[tid] - mu[tid] * s;
    }
    __syncthreads();

    float win[27];
#pragma unroll
    for (int ci = 0; ci < 3; ci++)
#pragma unroll
        for (int ky = 0; ky < 3; ky++)
#pragma unroll
            for (int kx = 0; kx < 3; kx++)
                win[(ci*3 + ky)*3 + kx] = xs[ci][threadIdx.y + ky][threadIdx.x + kx];

    const int y = y0 + threadIdx.y, xg = x0 + threadIdx.x;
    for (int oc = 0; oc < 64; oc++) {
        float acc = 0.f;
#pragma unroll
        for (int i = 0; i < 27; i++) acc = fmaf(ws[oc*27 + i], win[i], acc);
        float t = acc * sc[oc] + sh[oc];
        g_f1[((b*64 + oc)*HH + y)*HH + xg] = gelu_f(t);
    }
}

// ---------------- conv2: 64->64, 3x3, pad1, + BN + GELU (R11 winner) --------------
__global__ __launch_bounds__(256, 2)
void conv2_kernel(const float* __restrict__ w,
                  const float* __restrict__ gma, const float* __restrict__ bta,
                  const float* __restrict__ mu,  const float* __restrict__ var)
{
    __shared__ float ti[2][66][18];
    __shared__ float wall[16*576];
    __shared__ float sc[16], sh[16];
    const int tx = threadIdx.x, ty = threadIdx.y;
    const int tid = ty * 16 + tx;
    const int bz = blockIdx.z;
    const int b = bz >> 2, ocb = (bz & 3) * 16;
    const int y0 = blockIdx.y * 64, x0 = blockIdx.x * 16;

    if (tid < 16) {
        int oc = ocb + tid;
        float s = gma[oc] * rsqrtf(var[oc] + 1e-5f);
        sc[tid] = s; sh[tid] = bta[oc] - mu[oc] * s;
    }
    for (int i = tid; i < 16*576; i += 256)
        wall[i] = w[(ocb + (i / 576))*576 + (i % 576)];

    float acc[4][16];
#pragma unroll
    for (int r = 0; r < 4; r++)
#pragma unroll
        for (int o = 0; o < 16; o++) acc[r][o] = 0.f;

    auto load_tile_regs = [&](int ci, float* rg) {
#pragma unroll
        for (int k = 0; k < 5; k++) {
            int i = tid + k*256;
            float v = 0.f;
            if (i < 66*18) {
                int r = i / 18, cc = i % 18;
                int yy = y0 - 1 + r, xx = x0 - 1 + cc;
                if (yy >= 0 && yy < HH && xx >= 0 && xx < HH)
                    v = g_f1[((b*64 + ci)*HH + yy)*HH + xx];
            }
            rg[k] = v;
        }
    };
    auto store_tile = [&](int buf, const float* rg) {
#pragma unroll
        for (int k = 0; k < 5; k++) {
            int i = tid + k*256;
            if (i < 66*18) ti[buf][i / 18][i % 18] = rg[k];
        }
    };

    float rg[5];
    load_tile_regs(0, rg);
    store_tile(0, rg);
    __syncthreads();

    for (int ci = 0; ci < 64; ci++) {
        const int buf = ci & 1;
        if (ci < 63) load_tile_regs(ci + 1, rg);

        float win[4][9];
#pragma unroll
        for (int r = 0; r < 4; r++)
#pragma unroll
            for (int ky = 0; ky < 3; ky++)
#pragma unroll
                for (int kx = 0; kx < 3; kx++)
                    win[r][ky*3 + kx] = ti[buf][ty + 16*r + ky][tx + kx];

        const float* wrow = &wall[ci*9];
#pragma unroll
        for (int o = 0; o < 16; o++) {
#pragma unroll
            for (int j = 0; j < 9; j++) {
                float wv = wrow[o*576 + j];
#pragma unroll
                for (int r = 0; r < 4; r++)
                    acc[r][o] = fmaf(wv, win[r][j], acc[r][o]);
            }
        }

        if (ci < 63) {
            store_tile(buf ^ 1, rg);
            __syncthreads();
        }
    }

#pragma unroll
    for (int r = 0; r < 4; r++) {
        int y = y0 + ty + 16*r;
#pragma unroll
        for (int o = 0; o < 16; o++) {
            float t = acc[r][o] * sc[o] + sh[o];
            g_f2[((b*64 + ocb + o)*HH + y)*HH + x0 + tx] = gelu_f(t);
        }
    }
}

// ---------------- WMMA fp16 implicit GEMM: 128x128 tile, BK=64, double-buffered ----
// MODE 0: coarse  (A = 16x16 patches of f2, split-K via blockIdx.z) -> g_part[z]
// MODE 1: detail@topk (A = 8x8 patches at gathered positions, K=4096) -> g_dgath
// MODE 2: merge   (A = g_dgath rows, K=3072, M=1024) -> out
#define LDAH 72   // smem leading dim in halves; 72*2=144B rows, 16B-aligned

template<int MODE>
__global__ __launch_bounds__(256, 2)
void wmma_gemm(const float* __restrict__ W, float* __restrict__ out)
{
    constexpr int KTOT = (MODE == 0) ? 16384 : ((MODE == 1) ? 4096 : 3072);
    constexpr int KSPL = (MODE == 0) ? 8192 : KTOT;   // per-z K range
    constexpr int NCH  = KSPL / 64;

    __shared__ __align__(16) __half As[2][128*LDAH];
    __shared__ __align__(16) __half Bs[2][128*LDAH];

    const int tid = threadIdx.x;
    const int wid = tid >> 5;
    const int bm = blockIdx.y, bn = blockIdx.x;
    const int kbase = (MODE == 0) ? (int)blockIdx.z * KSPL : 0;

    const int lr = tid >> 1;          // A/B row within tile
    const int kq = (tid & 1) * 32;    // k sub-32 selector
    const int arow = bm * 128 + lr;
    const int brow = bn * 128 + lr;

    long baseA = 0;
    if (MODE == 0) {
        int b = arow / 576; int cell = arow % 576;
        baseA = ((long)(b*64)*HH + (cell/24)*16)*HH + (cell%24)*16;
    } else if (MODE == 1) {
        int b = arow >> 8, kk = (arow >> 2) & 63, dyx = arow & 3;
        int cell = g_topk[b*64 + kk];
        int y48 = 2*(cell/24) + (dyx >> 1);
        int x48 = 2*(cell%24) + (dyx & 1);
        baseA = ((long)(b*64)*HH + y48*8)*HH + x48*8;
    } else {
        baseA = (long)arow * 3072;
    }
    const float* wp = W + (long)brow * KTOT;

    const int wm = (wid & 1) * 64;
    const int wn = (wid >> 1) * 32;

    wmma::fragment<wmma::accumulator, 16, 16, 16, float> acc[4][2];
#pragma unroll
    for (int i = 0; i < 4; i++)
#pragma unroll
        for (int j = 0; j < 2; j++) wmma::fill_fragment(acc[i][j], 0.f);

    const uint32_t soff = lr*LDAH + kq;   // in halves

    auto load_chunk = [&](int kc, int buf) {
        uint32_t pa[16], pb[16];
#pragma unroll
        for (int j = 0; j < 8; j++) {
            const int k0 = kbase + kc + kq + j*4;
            const float* ap;
            if (MODE == 0) {
                int c = k0 >> 8; int rem = k0 & 255;
                ap = g_f2 + baseA + (long)c*(HH*HH) + (rem >> 4)*HH + (rem & 15);
            } else if (MODE == 1) {
                int c = k0 >> 6; int rem = k0 & 63;
                ap = g_f2 + baseA + (long)c*(HH*HH) + (rem >> 3)*HH + (rem & 7);
            } else {
                ap = g_dgath + baseA + k0;
            }
            float4 a = *(const float4*)ap;
            float4 b = *(const float4*)(wp + k0);
            __half2 a01 = __floats2half2_rn(a.x, a.y);
            __half2 a23 = __floats2half2_rn(a.z, a.w);
            __half2 b01 = __floats2half2_rn(b.x, b.y);
            __half2 b23 = __floats2half2_rn(b.z, b.w);
            pa[2*j]   = *(uint32_t*)&a01; pa[2*j+1] = *(uint32_t*)&a23;
            pb[2*j]   = *(uint32_t*)&b01; pb[2*j+1] = *(uint32_t*)&b23;
        }
#pragma unroll
        for (int q = 0; q < 4; q++) {
            *(uint4*)&As[buf][soff + q*8] = make_uint4(pa[4*q], pa[4*q+1], pa[4*q+2], pa[4*q+3]);
            *(uint4*)&Bs[buf][soff + q*8] = make_uint4(pb[4*q], pb[4*q+1], pb[4*q+2], pb[4*q+3]);
        }
    };

    load_chunk(0, 0);
    __syncthreads();

    for (int i = 0; i < NCH; i++) {
        const int buf = i & 1;
        if (i + 1 < NCH) load_chunk((i + 1) * 64, buf ^ 1);

#pragma unroll
        for (int ks = 0; ks < 4; ks++) {
            wmma::fragment<wmma::matrix_a, 16, 16, 16, half, wmma::row_major> af[4];
            wmma::fragment<wmma::matrix_b, 16, 16, 16, half, wmma::col_major> bf[2];
#pragma unroll
            for (int mi = 0; mi < 4; mi++)
                wmma::load_matrix_sync(af[mi], &As[buf][(wm + 16*mi)*LDAH + ks*16], LDAH);
#pragma unroll
            for (int nj = 0; nj < 2; nj++)
                wmma::load_matrix_sync(bf[nj], &Bs[buf][(wn + 16*nj)*LDAH + ks*16], LDAH);
#pragma unroll
            for (int mi = 0; mi < 4; mi++)
#pragma unroll
                for (int nj = 0; nj < 2; nj++)
                    wmma::mma_sync(acc[mi][nj], af[mi], bf[nj], acc[mi][nj]);
        }
        __syncthreads();
    }

    float* op;
    if (MODE == 0)      op = g_part[blockIdx.z];
    else if (MODE == 1) op = g_dgath;
    else                op = out;
#pragma unroll
    for (int mi = 0; mi < 4; mi++)
#pragma unroll
        for (int nj = 0; nj < 2; nj++) {
            long mrow = (long)bm*128 + wm + 16*mi;
            int ncol = bn*128 + wn + 16*nj;
            wmma::store_matrix_sync(&op[mrow*768 + ncol], acc[mi][nj], 768, wmma::mem_row_major);
        }
}

// ---------------- coarse reduce: out = part0 + part1 + bias ----------------
__global__ void reduce_bias_kernel(float* __restrict__ out, const float* __restrict__ bias, int n4)
{
    int i = blockIdx.x * blockDim.x + threadIdx.x;
    if (i >= n4) return;
    float4 p0 = ((const float4*)g_part[0])[i];
    float4 p1 = ((const float4*)g_part[1])[i];
    int nb = (i * 4) % 768;
    float4 b = *(const float4*)&bias[nb];
    float4 v;
    v.x = p0.x + p1.x + b.x; v.y = p0.y + p1.y + b.y;
    v.z = p0.z + p1.z + b.z; v.w = p0.w + p1.w + b.w;
    ((float4*)out)[i] = v;
}

__global__ void add_mbias_kernel(float* __restrict__ out, int n4)
{
    int i = blockIdx.x * blockDim.x + threadIdx.x;
    if (i >= n4) return;
    float4 v = ((float4*)out)[i];
    int nb = (i * 4) % 768;
    float4 b = *(const float4*)&g_mbias[nb];
    v.x += b.x; v.y += b.y; v.z += b.z; v.w += b.w;
    ((float4*)out)[i] = v;
}

// g_mbias[n] = merge_b[n] + sum_k detail_b[k % 768] * merge_w[n][k]
__global__ void mbias_kernel(const float* __restrict__ merge_w, const float* __restrict__ merge_b,
                             const float* __restrict__ detail_b)
{
    const int n = blockIdx.x;
    const int tid = threadIdx.x;
    const float* wr = merge_w + (long)n * 3072;
    float s = 0.f;
    for (int k = tid; k < 3072; k += 256)
        s = fmaf(detail_b[k % 768], wr[k], s);
    __shared__ float red[256];
    red[tid] = s;
    __syncthreads();
    for (int off = 128; off > 0; off >>= 1) {
        if (tid < off) red[tid] += red[tid + off];
        __syncthreads();
    }
    if (tid == 0) g_mbias[n] = merge_b[n] + red[0];
}

// ---------------- per-patch variance score (exact fp32 NCHW) ----------------
__global__ void score_kernel()
{
    const int bi = blockIdx.x;           // b*576 + cell
    const int b = bi / 576, cell = bi % 576;
    const int gy = cell / 24, gx = cell % 24;
    const int tid = threadIdx.x;
    const int c = tid >> 2, q = tid & 3;
    const float* base = g_f2 + ((size_t)(b*64 + c)*HH + gy*16)*HH + gx*16 + q*4;
    float s = 0.f, ss = 0.f;
#pragma unroll
    for (int i = 0; i < 16; i++) {
        float4 v = *(const float4*)(base + i*HH);
        s += v.x + v.y + v.z + v.w;
        ss = fmaf(v.x, v.x, ss); ss = fmaf(v.y, v.y, ss);
        ss = fmaf(v.z, v.z, ss); ss = fmaf(v.w, v.w, ss);
    }
    s  += __shfl_down_sync(0xffffffffu, s, 2);
    s  += __shfl_down_sync(0xffffffffu, s, 1);
    ss += __shfl_down_sync(0xffffffffu, ss, 2);
    ss += __shfl_down_sync(0xffffffffu, ss, 1);
    __shared__ float cv[64];
    if ((tid & 3) == 0) {
        float mean = s * (1.f/256.f);
        cv[c] = ss * (1.f/256.f) - mean*mean;
    }
    __syncthreads();
    if (tid < 32) {
        float v = cv[tid] + cv[tid + 32];
        for (int off = 16; off > 0; off >>= 1)
            v += __shfl_down_sync(0xffffffffu, v, off);
        if (tid == 0) g_scores[bi] = v * (1.f/64.f);
    }
}

// ---------------- top-64 of 576, descending, ties -> lowest index ----------------
__global__ void topk_kernel(float* __restrict__ out_idx)
{
    const int b = blockIdx.x, tid = threadIdx.x;
    __shared__ float s[576];
    __shared__ float rv[256];
    __shared__ int   ri[256];
    for (int i = tid; i < 576; i += 256) s[i] = g_scores[b*576 + i];
    __syncthreads();
    for (int k = 0; k < 64; k++) {
        float bv = s[tid]; int bidx = tid;
        if (tid + 256 < 576) { float v = s[tid + 256]; if (v > bv) { bv = v; bidx = tid + 256; } }
        if (tid + 512 < 576) { float v = s[tid + 512]; if (v > bv) { bv = v; bidx = tid + 512; } }
        rv[tid] = bv; ri[tid] = bidx;
        __syncthreads();
        for (int off = 128; off > 0; off >>= 1) {
            if (tid < off) {
                float v2 = rv[tid + off]; int i2 = ri[tid + off];
                if (v2 > rv[tid] || (v2 == rv[tid] && i2 < ri[tid])) { rv[tid] = v2; ri[tid] = i2; }
            }
            __syncthreads();
        }
        if (tid == 0) {
            int best = ri[0];
            g_topk[b*64 + k] = best;
            out_idx[b*64 + k] = (float)best;
            s[best] = -3.0e38f;
        }
        __syncthreads();
    }
}

// ---------------- launch ----------------
extern "C" void kernel_launch(void* const* d_in, const int* in_sizes, int n_in,
                              void* d_out, int out_size)
{
    (void)in_sizes; (void)n_in; (void)out_size;
    const float* x        = (const float*)d_in[0];
    const float* conv1_w  = (const float*)d_in[1];
    const float* bn1_g    = (const float*)d_in[2];
    const float* bn1_b    = (const float*)d_in[3];
    const float* bn1_m    = (const float*)d_in[4];
    const float* bn1_v    = (const float*)d_in[5];
    const float* conv2_w  = (const float*)d_in[6];
    const float* bn2_g    = (const float*)d_in[7];
    const float* bn2_b    = (const float*)d_in[8];
    const float* bn2_m    = (const float*)d_in[9];
    const float* bn2_v    = (const float*)d_in[10];
    const float* coarse_w = (const float*)d_in[11];
    const float* coarse_b = (const float*)d_in[12];
    const float* detail_w = (const float*)d_in[13];
    const float* detail_b = (const float*)d_in[14];
    const float* merge_w  = (const float*)d_in[15];
    const float* merge_b  = (const float*)d_in[16];
    float* out = (float*)d_out;

    const long OFF1 = 16L*576*768;            // coarse tokens
    const long OFF2 = OFF1 + 16L*64*768;      // detail tokens

    // launch order keeps the coarse GEMM at slot #4 (ncu capture slot)
    conv1_kernel<<<dim3(24,24,16), dim3(16,16)>>>(x, conv1_w, bn1_g, bn1_b, bn1_m, bn1_v);   // 1
    conv2_kernel<<<dim3(24,6,64),  dim3(16,16)>>>(conv2_w, bn2_g, bn2_b, bn2_m, bn2_v);      // 2

    score_kernel<<<9216, 256>>>();                                                           // 3
    wmma_gemm<0><<<dim3(6,72,2), 256>>>(coarse_w, nullptr);                                  // 4 (split-K)
    topk_kernel<<<16, 256>>>(out + OFF2);                                                    // 5
    mbias_kernel<<<768, 256>>>(merge_w, merge_b, detail_b);                                  // 6

    // detail conv ONLY at gathered top-k positions -> g_dgath [4096 x 768]
    wmma_gemm<1><<<dim3(6,32), 256>>>(detail_w, nullptr);                                    // 7
    // merge the gathered rows -> out[OFF1 .. OFF2), then += g_mbias
    wmma_gemm<2><<<dim3(6,8), 256>>>(merge_w, out + OFF1);                                   // 8

    // coarse: out = part0 + part1 + coarse_b
    reduce_bias_kernel<<<(9216*768/4 + 255)/256, 256>>>(out, coarse_b, 9216*768/4);          // 9
    add_mbias_kernel<<<(1024*768/4 + 255)/256, 256>>>(out + OFF1, 1024*768/4);               // 10
}

// round 15
// speedup vs baseline: 4.5512x; 1.0031x over previous
#include <cuda_runtime.h>
#include <cuda_fp16.h>
#include <math.h>
#include <stdint.h>
#include <mma.h>

using namespace nvcuda;

// ---------------- problem constants ----------------
#define HH 384
#define BB 16
#define CI 64
#define EE 768

// ---------------- scratch (device globals, no allocation) ----------------
__device__ float g_f1[(size_t)BB*CI*HH*HH];          // after conv1+bn+gelu
__device__ float g_f2[(size_t)BB*CI*HH*HH];          // after conv2+bn+gelu
__device__ float g_part[2][(size_t)9216*EE];         // coarse split-K partials
__device__ float g_dgath[(size_t)4096*EE];           // gathered detail conv outputs (no bias)
__device__ float g_scores[BB*576];
__device__ int   g_topk[BB*64];
__device__ float g_mbias[EE];                        // effective merge bias

__device__ __forceinline__ float gelu_f(float v) { return v * normcdff(v); }

// ---------------- conv1: 3->64, 3x3, pad1, + BN + GELU ----------------
__global__ void conv1_kernel(const float* __restrict__ x, const float* __restrict__ w,
                             const float* __restrict__ gma, const float* __restrict__ bta,
                             const float* __restrict__ mu,  const float* __restrict__ var)
{
    __shared__ float xs[3][18][18];
    __shared__ float ws[64*27];
    __shared__ float sc[64], sh[64];
    const int tid = threadIdx.y * 16 + threadIdx.x;
    const int b  = blockIdx.z;
    const int y0 = blockIdx.y * 16, x0 = blockIdx.x * 16;

    for (int i = tid; i < 3*18*18; i += 256) {
        int ci = i / 324, r = (i % 324) / 18, cc = i % 18;
        int yy = y0 - 1 + r, xx = x0 - 1 + cc;
        float v = 0.f;
        if (yy >= 0 && yy < HH && xx >= 0 && xx < HH)
            v = x[((b*3 + ci)*HH + yy)*HH + xx];
        xs[ci][r][cc] = v;
    }
    for (int i = tid; i < 64*27; i += 256) ws[i] = w[i];
    if (tid < 64) {
        float s = gma[tid] * rsqrtf(var[tid] + 1e-5f);
        sc[tid] = s; sh[tid] = bta[tid] - mu[tid] * s;
    }
    __syncthreads();

    float win[27];
#pragma unroll
    for (int ci = 0; ci < 3; ci++)
#pragma unroll
        for (int ky = 0; ky < 3; ky++)
#pragma unroll
            for (int kx = 0; kx < 3; kx++)
                win[(ci*3 + ky)*3 + kx] = xs[ci][threadIdx.y + ky][threadIdx.x + kx];

    const int y = y0 + threadIdx.y, xg = x0 + threadIdx.x;
    for (int oc = 0; oc < 64; oc++) {
        float acc = 0.f;
#pragma unroll
        for (int i = 0; i < 27; i++) acc = fmaf(ws[oc*27 + i], win[i], acc);
        float t = acc * sc[oc] + sh[oc];
        g_f1[((b*64 + oc)*HH + y)*HH + xg] = gelu_f(t);
    }
}

// ---------------- conv2: 64->64, 3x3, pad1, + BN + GELU (R11 winner) --------------
__global__ __launch_bounds__(256, 2)
void conv2_kernel(const float* __restrict__ w,
                  const float* __restrict__ gma, const float* __restrict__ bta,
                  const float* __restrict__ mu,  const float* __restrict__ var)
{
    __shared__ float ti[2][66][18];
    __shared__ float wall[16*576];
    __shared__ float sc[16], sh[16];
    const int tx = threadIdx.x, ty = threadIdx.y;
    const int tid = ty * 16 + tx;
    const int bz = blockIdx.z;
    const int b = bz >> 2, ocb = (bz & 3) * 16;
    const int y0 = blockIdx.y * 64, x0 = blockIdx.x * 16;

    if (tid < 16) {
        int oc = ocb + tid;
        float s = gma[oc] * rsqrtf(var[oc] + 1e-5f);
        sc[tid] = s; sh[tid] = bta[oc] - mu[oc] * s;
    }
    for (int i = tid; i < 16*576; i += 256)
        wall[i] = w[(ocb + (i / 576))*576 + (i % 576)];

    float acc[4][16];
#pragma unroll
    for (int r = 0; r < 4; r++)
#pragma unroll
        for (int o = 0; o < 16; o++) acc[r][o] = 0.f;

    auto load_tile_regs = [&](int ci, float* rg) {
#pragma unroll
        for (int k = 0; k < 5; k++) {
            int i = tid + k*256;
            float v = 0.f;
            if (i < 66*18) {
                int r = i / 18, cc = i % 18;
                int yy = y0 - 1 + r, xx = x0 - 1 + cc;
                if (yy >= 0 && yy < HH && xx >= 0 && xx < HH)
                    v = g_f1[((b*64 + ci)*HH + yy)*HH + xx];
            }
            rg[k] = v;
        }
    };
    auto store_tile = [&](int buf, const float* rg) {
#pragma unroll
        for (int k = 0; k < 5; k++) {
            int i = tid + k*256;
            if (i < 66*18) ti[buf][i / 18][i % 18] = rg[k];
        }
    };

    float rg[5];
    load_tile_regs(0, rg);
    store_tile(0, rg);
    __syncthreads();

    for (int ci = 0; ci < 64; ci++) {
        const int buf = ci & 1;
        if (ci < 63) load_tile_regs(ci + 1, rg);

        float win[4][9];
#pragma unroll
        for (int r = 0; r < 4; r++)
#pragma unroll
            for (int ky = 0; ky < 3; ky++)
#pragma unroll
                for (int kx = 0; kx < 3; kx++)
                    win[r][ky*3 + kx] = ti[buf][ty + 16*r + ky][tx + kx];

        const float* wrow = &wall[ci*9];
#pragma unroll
        for (int o = 0; o < 16; o++) {
#pragma unroll
            for (int j = 0; j < 9; j++) {
                float wv = wrow[o*576 + j];
#pragma unroll
                for (int r = 0; r < 4; r++)
                    acc[r][o] = fmaf(wv, win[r][j], acc[r][o]);
            }
        }

        if (ci < 63) {
            store_tile(buf ^ 1, rg);
            __syncthreads();
        }
    }

#pragma unroll
    for (int r = 0; r < 4; r++) {
        int y = y0 + ty + 16*r;
#pragma unroll
        for (int o = 0; o < 16; o++) {
            float t = acc[r][o] * sc[o] + sh[o];
            g_f2[((b*64 + ocb + o)*HH + y)*HH + x0 + tx] = gelu_f(t);
        }
    }
}

// ---------------- WMMA fp16 implicit GEMM: 128x128 tile, BK=64 ----------------
// 128 threads / 4 warps, 2x2 warp grid of 64x64 warp tiles (halves A-fragment
// LDS redundancy vs the 8x(64x32) layout; measured L1-bound at 92.7%).
// MODE 0: coarse  (A = 16x16 patches of f2, split-K via blockIdx.z) -> g_part[z]
// MODE 1: detail@topk (A = 8x8 patches at gathered positions, K=4096) -> g_dgath
// MODE 2: merge   (A = g_dgath rows, K=3072, M=1024) -> out
#define LDAH 72   // smem leading dim in halves; 72*2=144B rows, 16B-aligned

template<int MODE>
__global__ __launch_bounds__(128, 2)
void wmma_gemm(const float* __restrict__ W, float* __restrict__ out)
{
    constexpr int KTOT = (MODE == 0) ? 16384 : ((MODE == 1) ? 4096 : 3072);
    constexpr int KSPL = (MODE == 0) ? 8192 : KTOT;   // per-z K range
    constexpr int NCH  = KSPL / 64;

    __shared__ __align__(16) __half As[2][128*LDAH];
    __shared__ __align__(16) __half Bs[2][128*LDAH];

    const int tid = threadIdx.x;
    const int wid = tid >> 5;
    const int bm = blockIdx.y, bn = blockIdx.x;
    const int kbase = (MODE == 0) ? (int)blockIdx.z * KSPL : 0;

    const int lr = tid;               // each thread owns one full tile row (64 k)
    const int arow = bm * 128 + lr;
    const int brow = bn * 128 + lr;

    long baseA = 0;
    if (MODE == 0) {
        int b = arow / 576; int cell = arow % 576;
        baseA = ((long)(b*64)*HH + (cell/24)*16)*HH + (cell%24)*16;
    } else if (MODE == 1) {
        int b = arow >> 8, kk = (arow >> 2) & 63, dyx = arow & 3;
        int cell = g_topk[b*64 + kk];
        int y48 = 2*(cell/24) + (dyx >> 1);
        int x48 = 2*(cell%24) + (dyx & 1);
        baseA = ((long)(b*64)*HH + y48*8)*HH + x48*8;
    } else {
        baseA = (long)arow * 3072;
    }
    const float* wp = W + (long)brow * KTOT;

    // 2x2 warp grid of 64x64 tiles
    const int wm = (wid & 1) * 64;
    const int wn = (wid >> 1) * 64;

    wmma::fragment<wmma::accumulator, 16, 16, 16, float> acc[4][4];
#pragma unroll
    for (int i = 0; i < 4; i++)
#pragma unroll
        for (int j = 0; j < 4; j++) wmma::fill_fragment(acc[i][j], 0.f);

    const uint32_t soff = (uint32_t)lr * LDAH;   // in halves

    // loads one 32-k half (h = 0/1) of this thread's row for both A and B
    auto load_half = [&](int kc, int buf, int h) {
        uint32_t pa[8], pb[8];
        const int kh = kc + h*32;
#pragma unroll
        for (int j = 0; j < 8; j++) {
            const int k0 = kbase + kh + j*4;
            const float* ap;
            if (MODE == 0) {
                int c = k0 >> 8; int rem = k0 & 255;
                ap = g_f2 + baseA + (long)c*(HH*HH) + (rem >> 4)*HH + (rem & 15);
            } else if (MODE == 1) {
                int c = k0 >> 6; int rem = k0 & 63;
                ap = g_f2 + baseA + (long)c*(HH*HH) + (rem >> 3)*HH + (rem & 7);
            } else {
                ap = g_dgath + baseA + k0;
            }
            float4 a = *(const float4*)ap;
            float4 b = *(const float4*)(wp + k0);
            __half2 a01 = __floats2half2_rn(a.x, a.y);
            __half2 a23 = __floats2half2_rn(a.z, a.w);
            __half2 b01 = __floats2half2_rn(b.x, b.y);
            __half2 b23 = __floats2half2_rn(b.z, b.w);
            pa[2*j]   = *(uint32_t*)&a01; pa[2*j+1] = *(uint32_t*)&a23;
            pb[2*j]   = *(uint32_t*)&b01; pb[2*j+1] = *(uint32_t*)&b23;
        }
#pragma unroll
        for (int q = 0; q < 2; q++) {
            *(uint4*)&As[buf][soff + h*32 + q*8] = make_uint4(pa[4*q], pa[4*q+1], pa[4*q+2], pa[4*q+3]);
            *(uint4*)&Bs[buf][soff + h*32 + q*8] = make_uint4(pb[4*q], pb[4*q+1], pb[4*q+2], pb[4*q+3]);
        }
        // remaining 16 halves
#pragma unroll
        for (int q = 2; q < 2; q++) {}
        *(uint4*)&As[buf][soff + h*32 + 16] = make_uint4(pa[8-8+4*2], 0, 0, 0); // placeholder (overwritten below)
    };
    (void)load_half; // not used — full-row loader below

    auto load_chunk = [&](int kc, int buf) {
#pragma unroll
        for (int h = 0; h < 2; h++) {
            uint32_t pa[16], pb[16];
#pragma unroll
            for (int j = 0; j < 8; j++) {
                const int k0 = kbase + kc + h*32 + j*4;
                const float* ap;
                if (MODE == 0) {
                    int c = k0 >> 8; int rem = k0 & 255;
                    ap = g_f2 + baseA + (long)c*(HH*HH) + (rem >> 4)*HH + (rem & 15);
                } else if (MODE == 1) {
                    int c = k0 >> 6; int rem = k0 & 63;
                    ap = g_f2 + baseA + (long)c*(HH*HH) + (rem >> 3)*HH + (rem & 7);
                } else {
                    ap = g_dgath + baseA + k0;
                }
                float4 a = *(const float4*)ap;
                float4 b = *(const float4*)(wp + k0);
                __half2 a01 = __floats2half2_rn(a.x, a.y);
                __half2 a23 = __floats2half2_rn(a.z, a.w);
                __half2 b01 = __floats2half2_rn(b.x, b.y);
                __half2 b23 = __floats2half2_rn(b.z, b.w);
                pa[2*j]   = *(uint32_t*)&a01; pa[2*j+1] = *(uint32_t*)&a23;
                pb[2*j]   = *(uint32_t*)&b01; pb[2*j+1] = *(uint32_t*)&b23;
            }
#pragma unroll
            for (int q = 0; q < 4; q++) {
                *(uint4*)&As[buf][soff + h*32 + q*8] = make_uint4(pa[4*q], pa[4*q+1], pa[4*q+2], pa[4*q+3]);
                *(uint4*)&Bs[buf][soff + h*32 + q*8] = make_uint4(pb[4*q], pb[4*q+1], pb[4*q+2], pb[4*q+3]);
            }
        }
    };

    load_chunk(0, 0);
    __syncthreads();

    for (int i = 0; i < NCH; i++) {
        const int buf = i & 1;
        if (i + 1 < NCH) load_chunk((i + 1) * 64, buf ^ 1);

#pragma unroll
        for (int ks = 0; ks < 4; ks++) {
            wmma::fragment<wmma::matrix_a, 16, 16, 16, half, wmma::row_major> af[4];
            wmma::fragment<wmma::matrix_b, 16, 16, 16, half, wmma::col_major> bf[4];
#pragma unroll
            for (int mi = 0; mi < 4; mi++)
                wmma::load_matrix_sync(af[mi], &As[buf][(wm + 16*mi)*LDAH + ks*16], LDAH);
#pragma unroll
            for (int nj = 0; nj < 4; nj++)
                wmma::load_matrix_sync(bf[nj], &Bs[buf][(wn + 16*nj)*LDAH + ks*16], LDAH);
#pragma unroll
            for (int mi = 0; mi < 4; mi++)
#pragma unroll
                for (int nj = 0; nj < 4; nj++)
                    wmma::mma_sync(acc[mi][nj], af[mi], bf[nj], acc[mi][nj]);
        }
        __syncthreads();
    }

    float* op;
    if (MODE == 0)      op = g_part[blockIdx.z];
    else if (MODE == 1) op = g_dgath;
    else                op = out;
#pragma unroll
    for (int mi = 0; mi < 4; mi++)
#pragma unroll
        for (int nj = 0; nj < 4; nj++) {
            long mrow = (long)bm*128 + wm + 16*mi;
            int ncol = bn*128 + wn + 16*nj;
            wmma::store_matrix_sync(&op[mrow*768 + ncol], acc[mi][nj], 768, wmma::mem_row_major);
        }
}

// ---------------- coarse reduce: out = part0 + part1 + bias ----------------
__global__ void reduce_bias_kernel(float* __restrict__ out, const float* __restrict__ bias, int n4)
{
    int i = blockIdx.x * blockDim.x + threadIdx.x;
    if (i >= n4) return;
    float4 p0 = ((const float4*)g_part[0])[i];
    float4 p1 = ((const float4*)g_part[1])[i];
    int nb = (i * 4) % 768;
    float4 b = *(const float4*)&bias[nb];
    float4 v;
    v.x = p0.x + p1.x + b.x; v.y = p0.y + p1.y + b.y;
    v.z = p0.z + p1.z + b.z; v.w = p0.w + p1.w + b.w;
    ((float4*)out)[i] = v;
}

__global__ void add_mbias_kernel(float* __restrict__ out, int n4)
{
    int i = blockIdx.x * blockDim.x + threadIdx.x;
    if (i >= n4) return;
    float4 v = ((float4*)out)[i];
    int nb = (i * 4) % 768;
    float4 b = *(const float4*)&g_mbias[nb];
    v.x += b.x; v.y += b.y; v.z += b.z; v.w += b.w;
    ((float4*)out)[i] = v;
}

// g_mbias[n] = merge_b[n] + sum_k detail_b[k % 768] * merge_w[n][k]
__global__ void mbias_kernel(const float* __restrict__ merge_w, const float* __restrict__ merge_b,
                             const float* __restrict__ detail_b)
{
    const int n = blockIdx.x;
    const int tid = threadIdx.x;
    const float* wr = merge_w + (long)n * 3072;
    float s = 0.f;
    for (int k = tid; k < 3072; k += 256)
        s = fmaf(detail_b[k % 768], wr[k], s);
    __shared__ float red[256];
    red[tid] = s;
    __syncthreads();
    for (int off = 128; off > 0; off >>= 1) {
        if (tid < off) red[tid] += red[tid + off];
        __syncthreads();
    }
    if (tid == 0) g_mbias[n] = merge_b[n] + red[0];
}

// ---------------- per-patch variance score (exact fp32 NCHW) ----------------
__global__ void score_kernel()
{
    const int bi = blockIdx.x;           // b*576 + cell
    const int b = bi / 576, cell = bi % 576;
    const int gy = cell / 24, gx = cell % 24;
    const int tid = threadIdx.x;
    const int c = tid >> 2, q = tid & 3;
    const float* base = g_f2 + ((size_t)(b*64 + c)*HH + gy*16)*HH + gx*16 + q*4;
    float s = 0.f, ss = 0.f;
#pragma unroll
    for (int i = 0; i < 16; i++) {
        float4 v = *(const float4*)(base + i*HH);
        s += v.x + v.y + v.z + v.w;
        ss = fmaf(v.x, v.x, ss); ss = fmaf(v.y, v.y, ss);
        ss = fmaf(v.z, v.z, ss); ss = fmaf(v.w, v.w, ss);
    }
    s  += __shfl_down_sync(0xffffffffu, s, 2);
    s  += __shfl_down_sync(0xffffffffu, s, 1);
    ss += __shfl_down_sync(0xffffffffu, ss, 2);
    ss += __shfl_down_sync(0xffffffffu, ss, 1);
    __shared__ float cv[64];
    if ((tid & 3) == 0) {
        float mean = s * (1.f/256.f);
        cv[c] = ss * (1.f/256.f) - mean*mean;
    }
    __syncthreads();
    if (tid < 32) {
        float v = cv[tid] + cv[tid + 32];
        for (int off = 16; off > 0; off >>= 1)
            v += __shfl_down_sync(0xffffffffu, v, off);
        if (tid == 0) g_scores[bi] = v * (1.f/64.f);
    }
}

// ---------------- top-64 of 576, descending, ties -> lowest index ----------------
__global__ void topk_kernel(float* __restrict__ out_idx)
{
    const int b = blockIdx.x, tid = threadIdx.x;
    __shared__ float s[576];
    __shared__ float rv[256];
    __shared__ int   ri[256];
    for (int i = tid; i < 576; i += 256) s[i] = g_scores[b*576 + i];
    __syncthreads();
    for (int k = 0; k < 64; k++) {
        float bv = s[tid]; int bidx = tid;
        if (tid + 256 < 576) { float v = s[tid + 256]; if (v > bv) { bv = v; bidx = tid + 256; } }
        if (tid + 512 < 576) { float v = s[tid + 512]; if (v > bv) { bv = v; bidx = tid + 512; } }
        rv[tid] = bv; ri[tid] = bidx;
        __syncthreads();
        for (int off = 128; off > 0; off >>= 1) {
            if (tid < off) {
                float v2 = rv[tid + off]; int i2 = ri[tid + off];
                if (v2 > rv[tid] || (v2 == rv[tid] && i2 < ri[tid])) { rv[tid] = v2; ri[tid] = i2; }
            }
            __syncthreads();
        }
        if (tid == 0) {
            int best = ri[0];
            g_topk[b*64 + k] = best;
            out_idx[b*64 + k] = (float)best;
            s[best] = -3.0e38f;
        }
        __syncthreads();
    }
}

// ---------------- launch ----------------
extern "C" void kernel_launch(void* const* d_in, const int* in_sizes, int n_in,
                              void* d_out, int out_size)
{
    (void)in_sizes; (void)n_in; (void)out_size;
    const float* x        = (const float*)d_in[0];
    const float* conv1_w  = (const float*)d_in[1];
    const float* bn1_g    = (const float*)d_in[2];
    const float* bn1_b    = (const float*)d_in[3];
    const float* bn1_m    = (const float*)d_in[4];
    const float* bn1_v    = (const float*)d_in[5];
    const float* conv2_w  = (const float*)d_in[6];
    const float* bn2_g    = (const float*)d_in[7];
    const float* bn2_b    = (const float*)d_in[8];
    const float* bn2_m    = (const float*)d_in[9];
    const float* bn2_v    = (const float*)d_in[10];
    const float* coarse_w = (const float*)d_in[11];
    const float* coarse_b = (const float*)d_in[12];
    const float* detail_w = (const float*)d_in[13];
    const float* detail_b = (const float*)d_in[14];
    const float* merge_w  = (const float*)d_in[15];
    const float* merge_b  = (const float*)d_in[16];
    float* out = (float*)d_out;

    const long OFF1 = 16L*576*768;            // coarse tokens
    const long OFF2 = OFF1 + 16L*64*768;      // detail tokens

    // launch order keeps the coarse GEMM at slot #4 (ncu capture slot)
    conv1_kernel<<<dim3(24,24,16), dim3(16,16)>>>(x, conv1_w, bn1_g, bn1_b, bn1_m, bn1_v);   // 1
    conv2_kernel<<<dim3(24,6,64),  dim3(16,16)>>>(conv2_w, bn2_g, bn2_b, bn2_m, bn2_v);      // 2

    score_kernel<<<9216, 256>>>();                                                           // 3
    wmma_gemm<0><<<dim3(6,72,2), 128>>>(coarse_w, nullptr);                                  // 4 (split-K)
    topk_kernel<<<16, 256>>>(out + OFF2);                                                    // 5
    mbias_kernel<<<768, 256>>>(merge_w, merge_b, detail_b);                                  // 6

    // detail conv ONLY at gathered top-k positions -> g_dgath [4096 x 768]
    wmma_gemm<1><<<dim3(6,32), 128>>>(detail_w, nullptr);                                    // 7
    // merge the gathered rows -> out[OFF1 .. OFF2), then += g_mbias
    wmma_gemm<2><<<dim3(6,8), 128>>>(merge_w, out + OFF1);                                   // 8

    // coarse: out = part0 + part1 + coarse_b
    reduce_bias_kernel<<<(9216*768/4 + 255)/256, 256>>>(out, coarse_b, 9216*768/4);          // 9
    add_mbias_kernel<<<(1024*768/4 + 255)/256, 256>>>(out + OFF1, 1024*768/4);               // 10
}

// round 17
// speedup vs baseline: 4.6099x; 1.0129x over previous
#include <cuda_runtime.h>
#include <cuda_fp16.h>
#include <math.h>
#include <stdint.h>
#include <mma.h>

using namespace nvcuda;

// ---------------- problem constants ----------------
#define HH 384
#define BB 16
#define CI 64
#define EE 768

// ---------------- scratch (device globals, no allocation) ----------------
__device__ float  g_f1[(size_t)BB*CI*HH*HH];          // after conv1+bn+gelu
__device__ float  g_f2[(size_t)BB*CI*HH*HH];          // after conv2+bn+gelu (fp32, exact)
__device__ __half g_f2h[(size_t)BB*CI*HH*HH];         // fp16 copy of f2 (GEMM A operand)
__device__ float  g_part[2][(size_t)9216*EE];         // coarse split-K partials
__device__ float  g_dgath[(size_t)4096*EE];           // gathered detail conv outputs
__device__ float  g_scores[BB*576];
__device__ int    g_topk[BB*64];
__device__ float  g_mbias[EE];                        // effective merge bias
__device__ __half g_cwh[(size_t)EE*16384];            // coarse w fp16 (same layout)
__device__ __half g_dwh[(size_t)EE*4096];             // detail w fp16
__device__ __half g_mwh[(size_t)EE*3072];             // merge w fp16

__device__ __forceinline__ float gelu_f(float v) { return v * normcdff(v); }

// ---------------- weights -> fp16 (elementwise, same layout) ----------------
__global__ void wconv_kernel(const float* __restrict__ cw, const float* __restrict__ dw,
                             const float* __restrict__ mw)
{
    const long n_c = (long)EE*16384, n_d = (long)EE*4096, n_m = (long)EE*3072;
    for (long i = (long)blockIdx.x * blockDim.x + threadIdx.x;
         i < n_c + n_d + n_m; i += (long)gridDim.x * blockDim.x) {
        if (i < n_c)              g_cwh[i] = __float2half_rn(cw[i]);
        else if (i < n_c + n_d)   g_dwh[i - n_c] = __float2half_rn(dw[i - n_c]);
        else                      g_mwh[i - n_c - n_d] = __float2half_rn(mw[i - n_c - n_d]);
    }
}

// ---------------- conv1: 3->64, 3x3, pad1, + BN + GELU ----------------
__global__ void conv1_kernel(const float* __restrict__ x, const float* __restrict__ w,
                             const float* __restrict__ gma, const float* __restrict__ bta,
                             const float* __restrict__ mu,  const float* __restrict__ var)
{
    __shared__ float xs[3][18][18];
    __shared__ float ws[64*27];
    __shared__ float sc[64], sh[64];
    const int tid = threadIdx.y * 16 + threadIdx.x;
    const int b  = blockIdx.z;
    const int y0 = blockIdx.y * 16, x0 = blockIdx.x * 16;

    for (int i = tid; i < 3*18*18; i += 256) {
        int ci = i / 324, r = (i % 324) / 18, cc = i % 18;
        int yy = y0 - 1 + r, xx = x0 - 1 + cc;
        float v = 0.f;
        if (yy >= 0 && yy < HH && xx >= 0 && xx < HH)
            v = x[((b*3 + ci)*HH + yy)*HH + xx];
        xs[ci][r][cc] = v;
    }
    for (int i = tid; i < 64*27; i += 256) ws[i] = w[i];
    if (tid < 64) {
        float s = gma[tid] * rsqrtf(var[tid] + 1e-5f);
        sc[tid] = s; sh[tid] = bta[tid] - mu[tid] * s;
    }
    __syncthreads();

    float win[27];
#pragma unroll
    for (int ci = 0; ci < 3; ci++)
#pragma unroll
        for (int ky = 0; ky < 3; ky++)
#pragma unroll
            for (int kx = 0; kx < 3; kx++)
                win[(ci*3 + ky)*3 + kx] = xs[ci][threadIdx.y + ky][threadIdx.x + kx];

    const int y = y0 + threadIdx.y, xg = x0 + threadIdx.x;
    for (int oc = 0; oc < 64; oc++) {
        float acc = 0.f;
#pragma unroll
        for (int i = 0; i < 27; i++) acc = fmaf(ws[oc*27 + i], win[i], acc);
        float t = acc * sc[oc] + sh[oc];
        g_f1[((b*64 + oc)*HH + y)*HH + xg] = gelu_f(t);
    }
}

// ---------------- conv2: fp32 exact + fp16 shadow store --------------------------
__global__ __launch_bounds__(256, 2)
void conv2_kernel(const float* __restrict__ w,
                  const float* __restrict__ gma, const float* __restrict__ bta,
                  const float* __restrict__ mu,  const float* __restrict__ var)
{
    __shared__ float ti[2][66][18];
    __shared__ float wall[16*576];
    __shared__ float sc[16], sh[16];
    const int tx = threadIdx.x, ty = threadIdx.y;
    const int tid = ty * 16 + tx;
    const int bz = blockIdx.z;
    const int b = bz >> 2, ocb = (bz & 3) * 16;
    const int y0 = blockIdx.y * 64, x0 = blockIdx.x * 16;

    if (tid < 16) {
        int oc = ocb + tid;
        float s = gma[oc] * rsqrtf(var[oc] + 1e-5f);
        sc[tid] = s; sh[tid] = bta[oc] - mu[oc] * s;
    }
    for (int i = tid; i < 16*576; i += 256)
        wall[i] = w[(ocb + (i / 576))*576 + (i % 576)];

    float acc[4][16];
#pragma unroll
    for (int r = 0; r < 4; r++)
#pragma unroll
        for (int o = 0; o < 16; o++) acc[r][o] = 0.f;

    auto load_tile_regs = [&](int ci, float* rg) {
#pragma unroll
        for (int k = 0; k < 5; k++) {
            int i = tid + k*256;
            float v = 0.f;
            if (i < 66*18) {
                int r = i / 18, cc = i % 18;
                int yy = y0 - 1 + r, xx = x0 - 1 + cc;
                if (yy >= 0 && yy < HH && xx >= 0 && xx < HH)
                    v = g_f1[((b*64 + ci)*HH + yy)*HH + xx];
            }
            rg[k] = v;
        }
    };
    auto store_tile = [&](int buf, const float* rg) {
#pragma unroll
        for (int k = 0; k < 5; k++) {
            int i = tid + k*256;
            if (i < 66*18) ti[buf][i / 18][i % 18] = rg[k];
        }
    };

    float rg[5];
    load_tile_regs(0, rg);
    store_tile(0, rg);
    __syncthreads();

    for (int ci = 0; ci < 64; ci++) {
        const int buf = ci & 1;
        if (ci < 63) load_tile_regs(ci + 1, rg);

        float win[4][9];
#pragma unroll
        for (int r = 0; r < 4; r++)
#pragma unroll
            for (int ky = 0; ky < 3; ky++)
#pragma unroll
                for (int kx = 0; kx < 3; kx++)
                    win[r][ky*3 + kx] = ti[buf][ty + 16*r + ky][tx + kx];

        const float* wrow = &wall[ci*9];
#pragma unroll
        for (int o = 0; o < 16; o++) {
#pragma unroll
            for (int j = 0; j < 9; j++) {
                float wv = wrow[o*576 + j];
#pragma unroll
                for (int r = 0; r < 4; r++)
                    acc[r][o] = fmaf(wv, win[r][j], acc[r][o]);
            }
        }

        if (ci < 63) {
            store_tile(buf ^ 1, rg);
            __syncthreads();
        }
    }

#pragma unroll
    for (int r = 0; r < 4; r++) {
        int y = y0 + ty + 16*r;
#pragma unroll
        for (int o = 0; o < 16; o++) {
            float t = acc[r][o] * sc[o] + sh[o];
            float g = gelu_f(t);
            size_t idx = ((size_t)(b*64 + ocb + o)*HH + y)*HH + x0 + tx;
            g_f2[idx]  = g;
            g_f2h[idx] = __float2half_rn(g);
        }
    }
}

// ---------------- WMMA fp16 implicit GEMM: 128x128 tile, BK=64 ----------------
// 128 threads / 4 warps, 2x2 warp grid of 64x64 tiles.
// fp16 operands loaded directly (producer-converted): no CVT, half the LDG bytes.
// Weight arrays selected INSIDE the kernel by MODE (device-global access).
// MODE 0: coarse  (A = g_f2h 16x16 patches, split-K via blockIdx.z) -> g_part[z]
// MODE 1: detail@topk (A = g_f2h 8x8 patches at gathered positions) -> g_dgath
// MODE 2: merge   (A = g_dgath fp32 rows + CVT, K=3072) -> out
#define LDAH 72   // smem leading dim in halves; 144B rows

template<int MODE>
__global__ __launch_bounds__(128, 2)
void wmma_gemm(float* __restrict__ out)
{
    constexpr int KTOT = (MODE == 0) ? 16384 : ((MODE == 1) ? 4096 : 3072);
    constexpr int KSPL = (MODE == 0) ? 8192 : KTOT;
    constexpr int NCH  = KSPL / 64;

    __shared__ __align__(16) __half As[2][128*LDAH];
    __shared__ __align__(16) __half Bs[2][128*LDAH];

    const int tid = threadIdx.x;
    const int wid = tid >> 5;
    const int bm = blockIdx.y, bn = blockIdx.x;
    const int kbase = (MODE == 0) ? (int)blockIdx.z * KSPL : 0;

    const int lr = tid;               // each thread owns one full tile row
    const int arow = bm * 128 + lr;
    const int brow = bn * 128 + lr;

    long baseA = 0;
    if (MODE == 0) {
        int b = arow / 576; int cell = arow % 576;
        baseA = ((long)(b*64)*HH + (cell/24)*16)*HH + (cell%24)*16;
    } else if (MODE == 1) {
        int b = arow >> 8, kk = (arow >> 2) & 63, dyx = arow & 3;
        int cell = g_topk[b*64 + kk];
        int y48 = 2*(cell/24) + (dyx >> 1);
        int x48 = 2*(cell%24) + (dyx & 1);
        baseA = ((long)(b*64)*HH + y48*8)*HH + x48*8;
    } else {
        baseA = (long)arow * 3072;
    }
    const __half* Wh = (MODE == 0) ? g_cwh : ((MODE == 1) ? g_dwh : g_mwh);
    const __half* wph = Wh + (long)brow * KTOT;

    const int wm = (wid & 1) * 64;
    const int wn = (wid >> 1) * 64;

    wmma::fragment<wmma::accumulator, 16, 16, 16, float> acc[4][4];
#pragma unroll
    for (int i = 0; i < 4; i++)
#pragma unroll
        for (int j = 0; j < 4; j++) wmma::fill_fragment(acc[i][j], 0.f);

    const uint32_t soff = (uint32_t)lr * LDAH;

    auto load_chunk = [&](int kc, int buf) {
#pragma unroll
        for (int h = 0; h < 2; h++) {
            uint32_t pa[16], pb[16];
#pragma unroll
            for (int j = 0; j < 8; j++) {
                const int k0 = kbase + kc + h*32 + j*4;
                if (MODE == 2) {
                    float4 a = *(const float4*)(g_dgath + baseA + k0);
                    __half2 a01 = __floats2half2_rn(a.x, a.y);
                    __half2 a23 = __floats2half2_rn(a.z, a.w);
                    pa[2*j]   = *(uint32_t*)&a01;
                    pa[2*j+1] = *(uint32_t*)&a23;
                } else {
                    const __half* ap;
                    if (MODE == 0) {
                        int c = k0 >> 8; int rem = k0 & 255;
                        ap = g_f2h + baseA + (long)c*(HH*HH) + (rem >> 4)*HH + (rem & 15);
                    } else {
                        int c = k0 >> 6; int rem = k0 & 63;
                        ap = g_f2h + baseA + (long)c*(HH*HH) + (rem >> 3)*HH + (rem & 7);
                    }
                    uint2 a = *(const uint2*)ap;
                    pa[2*j]   = a.x;
                    pa[2*j+1] = a.y;
                }
                uint2 b = *(const uint2*)(wph + k0);
                pb[2*j]   = b.x;
                pb[2*j+1] = b.y;
            }
#pragma unroll
            for (int q = 0; q < 4; q++) {
                *(uint4*)&As[buf][soff + h*32 + q*8] = make_uint4(pa[4*q], pa[4*q+1], pa[4*q+2], pa[4*q+3]);
                *(uint4*)&Bs[buf][soff + h*32 + q*8] = make_uint4(pb[4*q], pb[4*q+1], pb[4*q+2], pb[4*q+3]);
            }
        }
    };

    load_chunk(0, 0);
    __syncthreads();

    for (int i = 0; i < NCH; i++) {
        const int buf = i & 1;
        if (i + 1 < NCH) load_chunk((i + 1) * 64, buf ^ 1);

#pragma unroll
        for (int ks = 0; ks < 4; ks++) {
            wmma::fragment<wmma::matrix_a, 16, 16, 16, half, wmma::row_major> af[4];
            wmma::fragment<wmma::matrix_b, 16, 16, 16, half, wmma::col_major> bf[4];
#pragma unroll
            for (int mi = 0; mi < 4; mi++)
                wmma::load_matrix_sync(af[mi], &As[buf][(wm + 16*mi)*LDAH + ks*16], LDAH);
#pragma unroll
            for (int nj = 0; nj < 4; nj++)
                wmma::load_matrix_sync(bf[nj], &Bs[buf][(wn + 16*nj)*LDAH + ks*16], LDAH);
#pragma unroll
            for (int mi = 0; mi < 4; mi++)
#pragma unroll
                for (int nj = 0; nj < 4; nj++)
                    wmma::mma_sync(acc[mi][nj], af[mi], bf[nj], acc[mi][nj]);
        }
        __syncthreads();
    }

    float* op;
    if (MODE == 0)      op = g_part[blockIdx.z];
    else if (MODE == 1) op = g_dgath;
    else                op = out;
#pragma unroll
    for (int mi = 0; mi < 4; mi++)
#pragma unroll
        for (int nj = 0; nj < 4; nj++) {
            long mrow = (long)bm*128 + wm + 16*mi;
            int ncol = bn*128 + wn + 16*nj;
            wmma::store_matrix_sync(&op[mrow*768 + ncol], acc[mi][nj], 768, wmma::mem_row_major);
        }
}

// ---------------- coarse reduce: out = part0 + part1 + bias ----------------
__global__ void reduce_bias_kernel(float* __restrict__ out, const float* __restrict__ bias, int n4)
{
    int i = blockIdx.x * blockDim.x + threadIdx.x;
    if (i >= n4) return;
    float4 p0 = ((const float4*)g_part[0])[i];
    float4 p1 = ((const float4*)g_part[1])[i];
    int nb = (i * 4) % 768;
    float4 b = *(const float4*)&bias[nb];
    float4 v;
    v.x = p0.x + p1.x + b.x; v.y = p0.y + p1.y + b.y;
    v.z = p0.z + p1.z + b.z; v.w = p0.w + p1.w + b.w;
    ((float4*)out)[i] = v;
}

__global__ void add_mbias_kernel(float* __restrict__ out, int n4)
{
    int i = blockIdx.x * blockDim.x + threadIdx.x;
    if (i >= n4) return;
    float4 v = ((float4*)out)[i];
    int nb = (i * 4) % 768;
    float4 b = *(const float4*)&g_mbias[nb];
    v.x += b.x; v.y += b.y; v.z += b.z; v.w += b.w;
    ((float4*)out)[i] = v;
}

// g_mbias[n] = merge_b[n] + sum_k detail_b[k % 768] * merge_w[n][k]
__global__ void mbias_kernel(const float* __restrict__ merge_w, const float* __restrict__ merge_b,
                             const float* __restrict__ detail_b)
{
    const int n = blockIdx.x;
    const int tid = threadIdx.x;
    const float* wr = merge_w + (long)n * 3072;
    float s = 0.f;
    for (int k = tid; k < 3072; k += 256)
        s = fmaf(detail_b[k % 768], wr[k], s);
    __shared__ float red[256];
    red[tid] = s;
    __syncthreads();
    for (int off = 128; off > 0; off >>= 1) {
        if (tid < off) red[tid] += red[tid + off];
        __syncthreads();
    }
    if (tid == 0) g_mbias[n] = merge_b[n] + red[0];
}

// ---------------- per-patch variance score (exact fp32 NCHW) ----------------
__global__ void score_kernel()
{
    const int bi = blockIdx.x;           // b*576 + cell
    const int b = bi / 576, cell = bi % 576;
    const int gy = cell / 24, gx = cell % 24;
    const int tid = threadIdx.x;
    const int c = tid >> 2, q = tid & 3;
    const float* base = g_f2 + ((size_t)(b*64 + c)*HH + gy*16)*HH + gx*16 + q*4;
    float s = 0.f, ss = 0.f;
#pragma unroll
    for (int i = 0; i < 16; i++) {
        float4 v = *(const float4*)(base + i*HH);
        s += v.x + v.y + v.z + v.w;
        ss = fmaf(v.x, v.x, ss); ss = fmaf(v.y, v.y, ss);
        ss = fmaf(v.z, v.z, ss); ss = fmaf(v.w, v.w, ss);
    }
    s  += __shfl_down_sync(0xffffffffu, s, 2);
    s  += __shfl_down_sync(0xffffffffu, s, 1);
    ss += __shfl_down_sync(0xffffffffu, ss, 2);
    ss += __shfl_down_sync(0xffffffffu, ss, 1);
    __shared__ float cv[64];
    if ((tid & 3) == 0) {
        float mean = s * (1.f/256.f);
        cv[c] = ss * (1.f/256.f) - mean*mean;
    }
    __syncthreads();
    if (tid < 32) {
        float v = cv[tid] + cv[tid + 32];
        for (int off = 16; off > 0; off >>= 1)
            v += __shfl_down_sync(0xffffffffu, v, off);
        if (tid == 0) g_scores[bi] = v * (1.f/64.f);
    }
}

// ---------------- top-64 of 576, descending, ties -> lowest index ----------------
__global__ void topk_kernel(float* __restrict__ out_idx)
{
    const int b = blockIdx.x, tid = threadIdx.x;
    __shared__ float s[576];
    __shared__ float rv[256];
    __shared__ int   ri[256];
    for (int i = tid; i < 576; i += 256) s[i] = g_scores[b*576 + i];
    __syncthreads();
    for (int k = 0; k < 64; k++) {
        float bv = s[tid]; int bidx = tid;
        if (tid + 256 < 576) { float v = s[tid + 256]; if (v > bv) { bv = v; bidx = tid + 256; } }
        if (tid + 512 < 576) { float v = s[tid + 512]; if (v > bv) { bv = v; bidx = tid + 512; } }
        rv[tid] = bv; ri[tid] = bidx;
        __syncthreads();
        for (int off = 128; off > 0; off >>= 1) {
            if (tid < off) {
                float v2 = rv[tid + off]; int i2 = ri[tid + off];
                if (v2 > rv[tid] || (v2 == rv[tid] && i2 < ri[tid])) { rv[tid] = v2; ri[tid] = i2; }
            }
            __syncthreads();
        }
        if (tid == 0) {
            int best = ri[0];
            g_topk[b*64 + k] = best;
            out_idx[b*64 + k] = (float)best;
            s[best] = -3.0e38f;
        }
        __syncthreads();
    }
}

// ---------------- launch ----------------
extern "C" void kernel_launch(void* const* d_in, const int* in_sizes, int n_in,
                              void* d_out, int out_size)
{
    (void)in_sizes; (void)n_in; (void)out_size;
    const float* x        = (const float*)d_in[0];
    const float* conv1_w  = (const float*)d_in[1];
    const float* bn1_g    = (const float*)d_in[2];
    const float* bn1_b    = (const float*)d_in[3];
    const float* bn1_m    = (const float*)d_in[4];
    const float* bn1_v    = (const float*)d_in[5];
    const float* conv2_w  = (const float*)d_in[6];
    const float* bn2_g    = (const float*)d_in[7];
    const float* bn2_b    = (const float*)d_in[8];
    const float* bn2_m    = (const float*)d_in[9];
    const float* bn2_v    = (const float*)d_in[10];
    const float* coarse_w = (const float*)d_in[11];
    const float* coarse_b = (const float*)d_in[12];
    const float* detail_w = (const float*)d_in[13];
    const float* detail_b = (const float*)d_in[14];
    const float* merge_w  = (const float*)d_in[15];
    const float* merge_b  = (const float*)d_in[16];
    float* out = (float*)d_out;

    const long OFF1 = 16L*576*768;            // coarse tokens
    const long OFF2 = OFF1 + 16L*64*768;      // detail tokens

    // launch order keeps the coarse GEMM at slot #4 (ncu capture slot)
    conv1_kernel<<<dim3(24,24,16), dim3(16,16)>>>(x, conv1_w, bn1_g, bn1_b, bn1_m, bn1_v);   // 1
    conv2_kernel<<<dim3(24,6,64),  dim3(16,16)>>>(conv2_w, bn2_g, bn2_b, bn2_m, bn2_v);      // 2
    wconv_kernel<<<1184, 256>>>(coarse_w, detail_w, merge_w);                                // 3
    wmma_gemm<0><<<dim3(6,72,2), 128>>>(nullptr);                                            // 4 (split-K)

    score_kernel<<<9216, 256>>>();                                                           // 5
    topk_kernel<<<16, 256>>>(out + OFF2);                                                    // 6
    mbias_kernel<<<768, 256>>>(merge_w, merge_b, detail_b);                                  // 7

    // detail conv ONLY at gathered top-k positions -> g_dgath [4096 x 768]
    wmma_gemm<1><<<dim3(6,32), 128>>>(nullptr);                                              // 8
    // merge the gathered rows -> out[OFF1 .. OFF2), then += g_mbias
    wmma_gemm<2><<<dim3(6,8), 128>>>(out + OFF1);                                            // 9

    // coarse: out = part0 + part1 + coarse_b
    reduce_bias_kernel<<<(9216*768/4 + 255)/256, 256>>>(out, coarse_b, 9216*768/4);          // 10
    add_mbias_kernel<<<(1024*768/4 + 255)/256, 256>>>(out + OFF1, 1024*768/4);               // 11
}